// round 10
// baseline (speedup 1.0000x reference)
#include <cuda_runtime.h>
#include <cuda_fp16.h>
#include <cstdint>
#include <math.h>

#define LN_EPS 1e-5f

// ---------------- device scratch ----------------
__device__ float g_CB0[128 * 512];
__device__ float g_MP0[64 * 512];
__device__ float g_AP0[8192 * 512];
__device__ uint32_t g_Wf[32768];          // W1 frag-packed fp16: [c4][s8][nf16][lane32][r2]
__device__ float g_scb[128], g_qcb[128];
__device__ float g_smp[64],  g_qmp[64];
__device__ float g_sap[8192], g_qap[8192];
__device__ float g_dapcb[8192 * 128];     // dot(AP0[bt], CB0[lat])
__device__ float g_dapmp[8192 * 64];      // dot(AP0[bt], MP0[m])
__device__ float g_dcm[128 * 64];         // dot(CB0[lat], MP0[m])

// ---------------- helpers ----------------
__device__ __forceinline__ uint32_t smem_u32(const void* p) {
    uint32_t a;
    asm("{ .reg .u64 t; cvta.to.shared.u64 t, %1; cvt.u32.u64 %0, t; }" : "=r"(a) : "l"(p));
    return a;
}
__device__ __forceinline__ void ldsm4(uint32_t (&r)[4], uint32_t addr) {
    asm volatile("ldmatrix.sync.aligned.m8n8.x4.shared.b16 {%0,%1,%2,%3}, [%4];"
        : "=r"(r[0]), "=r"(r[1]), "=r"(r[2]), "=r"(r[3]) : "r"(addr));
}
__device__ __forceinline__ void mma_f16(float (&d)[4], const uint32_t (&a)[4], uint2 b) {
    asm volatile("mma.sync.aligned.m16n8k16.row.col.f32.f16.f16.f32 "
        "{%0,%1,%2,%3}, {%4,%5,%6,%7}, {%8,%9}, {%0,%1,%2,%3};"
        : "+f"(d[0]), "+f"(d[1]), "+f"(d[2]), "+f"(d[3])
        : "r"(a[0]), "r"(a[1]), "r"(a[2]), "r"(a[3]), "r"(b.x), "r"(b.y));
}
__device__ __forceinline__ void blockReduce2_128(float& s, float& s2, float* red) {
#pragma unroll
    for (int off = 16; off > 0; off >>= 1) {
        s  += __shfl_xor_sync(0xffffffffu, s,  off);
        s2 += __shfl_xor_sync(0xffffffffu, s2, off);
    }
    int w = threadIdx.x >> 5;
    if ((threadIdx.x & 31) == 0) { red[w] = s; red[4 + w] = s2; }
    __syncthreads();
    s  = red[0] + red[1] + red[2] + red[3];
    s2 = red[4] + red[5] + red[6] + red[7];
    __syncthreads();
}

// ---------------- kernel: map_pos_embed MLP + projection (+ row stats) ----------------
__global__ __launch_bounds__(128) void k_mp(
    const float* __restrict__ mpl,
    const float* __restrict__ w0, const float* __restrict__ b0,
    const float* __restrict__ g0, const float* __restrict__ t0,
    const float* __restrict__ w1, const float* __restrict__ b1,
    const float* __restrict__ W0mla)
{
    __shared__ float xs[256], hs[128], mp[128], red[8];
    int m = blockIdx.x, j = threadIdx.x;
    xs[j] = mpl[m * 256 + j];
    xs[128 + j] = mpl[m * 256 + 128 + j];
    __syncthreads();

    float z = b0[j];
#pragma unroll 8
    for (int i = 0; i < 256; i++) z = fmaf(xs[i], w0[i * 128 + j], z);
    float s = z, s2 = z * z;
    blockReduce2_128(s, s2, red);
    float mean = s * (1.f / 128.f);
    float var = s2 * (1.f / 128.f) - mean * mean;
    float rs = rsqrtf(var + LN_EPS);
    hs[j] = fmaxf((z - mean) * rs * g0[j] + t0[j], 0.f);
    __syncthreads();

    float z1 = b1[j];
#pragma unroll 8
    for (int i = 0; i < 128; i++) z1 = fmaf(hs[i], w1[i * 128 + j], z1);
    mp[j] = z1;
    __syncthreads();

    float sl = 0.f, ql = 0.f;
#pragma unroll
    for (int q = 0; q < 4; q++) {
        int c = j + q * 128;
        float acc = 0.f;
#pragma unroll 8
        for (int i = 0; i < 128; i++) acc = fmaf(mp[i], W0mla[i * 512 + c], acc);
        g_MP0[m * 512 + c] = acc;
        sl += acc; ql += acc * acc;
    }
    blockReduce2_128(sl, ql, red);
    if (j == 0) { g_smp[m] = sl; g_qmp[m] = ql; }
}

// ---------------- kernel: codebook @ mla_w0 (+ row stats) ----------------
__global__ __launch_bounds__(128) void k_cb(
    const float* __restrict__ tok, const float* __restrict__ W0mla)
{
    __shared__ float cb[128], red[8];
    int lat = blockIdx.x, j = threadIdx.x;
    cb[j] = tok[lat * 128 + j];
    __syncthreads();
    float sl = 0.f, ql = 0.f;
#pragma unroll
    for (int q = 0; q < 4; q++) {
        int c = j + q * 128;
        float acc = 0.f;
#pragma unroll 8
        for (int i = 0; i < 128; i++) acc = fmaf(cb[i], W0mla[i * 512 + c], acc);
        g_CB0[lat * 512 + c] = acc;
        sl += acc; ql += acc * acc;
    }
    blockReduce2_128(sl, ql, red);
    if (j == 0) { g_scb[lat] = sl; g_qcb[lat] = ql; }
}

// ---------------- kernel: dot(CB0[lat], MP0[m]) ----------------
__global__ __launch_bounds__(128) void k_dcm() {
    __shared__ float mp[512];
    int m = blockIdx.x, j = threadIdx.x;
#pragma unroll
    for (int i = 0; i < 4; i++) mp[j + i * 128] = g_MP0[m * 512 + j + i * 128];
    __syncthreads();
    const float4* c4 = (const float4*)(g_CB0 + j * 512);
    const float4* m4 = (const float4*)mp;
    float d = 0.f;
#pragma unroll 8
    for (int i = 0; i < 128; i++) {
        float4 a = c4[i], b = m4[i];
        d += a.x * b.x + a.y * b.y + a.z * b.z + a.w * b.w;
    }
    g_dcm[j * 64 + m] = d;
}

// ---------------- 4-wide LN+ReLU helper ----------------
__device__ __forceinline__ void ln4(
    const float z[4], float gv, float tv, float (*dst)[128],
    float2 (*red)[4], int w, int l, int j)
{
    float s[4], q[4];
#pragma unroll
    for (int t = 0; t < 4; t++) { s[t] = z[t]; q[t] = z[t] * z[t]; }
#pragma unroll
    for (int off = 16; off > 0; off >>= 1) {
#pragma unroll
        for (int t = 0; t < 4; t++) {
            s[t] += __shfl_xor_sync(0xffffffffu, s[t], off);
            q[t] += __shfl_xor_sync(0xffffffffu, q[t], off);
        }
    }
    if (l == 0) {
#pragma unroll
        for (int t = 0; t < 4; t++) red[w][t] = make_float2(s[t], q[t]);
    }
    __syncthreads();
#pragma unroll
    for (int t = 0; t < 4; t++) {
        float ss = 0.f, qq = 0.f;
#pragma unroll
        for (int ww = 0; ww < 4; ww++) { float2 r = red[ww][t]; ss += r.x; qq += r.y; }
        float mean = ss * (1.f / 128.f);
        float var = qq * (1.f / 128.f) - mean * mean;
        float rs = rsqrtf(var + LN_EPS);
        dst[t][j] = fmaxf((z[t] - mean) * rs * gv + tv, 0.f);
    }
    __syncthreads();
}

// ---------------- kernel: agent_pos_emb MLP, 4 bt per block (+ stats) ----------------
__global__ __launch_bounds__(128) void k_ape4(
    const float* __restrict__ heading, const float* __restrict__ position,
    const float* __restrict__ w0, const float* __restrict__ b0,
    const float* __restrict__ g0, const float* __restrict__ t0,
    const float* __restrict__ w1, const float* __restrict__ b1,
    const float* __restrict__ g1, const float* __restrict__ t1,
    const float* __restrict__ w2, const float* __restrict__ b2,
    const float* __restrict__ W0mla, const float* __restrict__ b0mla)
{
    __shared__ float in_s[4][8];
    __shared__ float a_s[4][128];
    __shared__ float c_s[4][128];
    __shared__ float2 red_s[4][4];
    int j = threadIdx.x, w = j >> 5, l = j & 31;
    int bt0 = blockIdx.x * 4;

    if (j < 4) {
        int bt = bt0 + j, b = bt >> 7, t = bt & 127;
        float hd = heading[b * 4096 + t];
        float px = position[(b * 4096 + t) * 2 + 0];
        float py = position[(b * 4096 + t) * 2 + 1];
        in_s[j][0] = px; in_s[j][1] = py; in_s[j][2] = hd;
        in_s[j][3] = sinf(hd); in_s[j][4] = cosf(hd);
    }
    __syncthreads();

    float z[4];
    float bj = b0[j];
#pragma unroll
    for (int t = 0; t < 4; t++) z[t] = bj;
#pragma unroll
    for (int i = 0; i < 5; i++) {
        float wv = w0[i * 128 + j];
#pragma unroll
        for (int t = 0; t < 4; t++) z[t] = fmaf(in_s[t][i], wv, z[t]);
    }
    ln4(z, g0[j], t0[j], a_s, red_s, w, l, j);

    float bj1 = b1[j];
#pragma unroll
    for (int t = 0; t < 4; t++) z[t] = bj1;
#pragma unroll 4
    for (int i = 0; i < 128; i++) {
        float wv = w1[i * 128 + j];
#pragma unroll
        for (int t = 0; t < 4; t++) z[t] = fmaf(a_s[t][i], wv, z[t]);
    }
    ln4(z, g1[j], t1[j], c_s, red_s, w, l, j);

    float bj2 = b2[j];
#pragma unroll
    for (int t = 0; t < 4; t++) z[t] = bj2;
#pragma unroll 4
    for (int i = 0; i < 128; i++) {
        float wv = w2[i * 128 + j];
#pragma unroll
        for (int t = 0; t < 4; t++) z[t] = fmaf(c_s[t][i], wv, z[t]);
    }
    __syncthreads();
#pragma unroll
    for (int t = 0; t < 4; t++) a_s[t][j] = z[t];
    __syncthreads();

    float s_loc[4] = {0.f, 0.f, 0.f, 0.f};
    float q_loc[4] = {0.f, 0.f, 0.f, 0.f};
#pragma unroll
    for (int qd = 0; qd < 4; qd++) {
        int c = j + qd * 128;
        float acc[4];
        float bc = b0mla[c];
#pragma unroll
        for (int t = 0; t < 4; t++) acc[t] = bc;
#pragma unroll 4
        for (int i = 0; i < 128; i++) {
            float wv = W0mla[i * 512 + c];
#pragma unroll
            for (int t = 0; t < 4; t++) acc[t] = fmaf(a_s[t][i], wv, acc[t]);
        }
#pragma unroll
        for (int t = 0; t < 4; t++) {
            g_AP0[(bt0 + t) * 512 + c] = acc[t];
            s_loc[t] += acc[t];
            q_loc[t] += acc[t] * acc[t];
        }
    }
    // reduce stats across 128 threads for each of 4 tokens
#pragma unroll
    for (int off = 16; off > 0; off >>= 1) {
#pragma unroll
        for (int t = 0; t < 4; t++) {
            s_loc[t] += __shfl_xor_sync(0xffffffffu, s_loc[t], off);
            q_loc[t] += __shfl_xor_sync(0xffffffffu, q_loc[t], off);
        }
    }
    if (l == 0) {
#pragma unroll
        for (int t = 0; t < 4; t++) red_s[w][t] = make_float2(s_loc[t], q_loc[t]);
    }
    __syncthreads();
    if (j < 4) {
        float ss = 0.f, qq = 0.f;
#pragma unroll
        for (int ww = 0; ww < 4; ww++) { float2 r = red_s[ww][j]; ss += r.x; qq += r.y; }
        g_sap[bt0 + j] = ss;
        g_qap[bt0 + j] = qq;
    }
}

// ---------------- kernel: cross dots AP0 x {CB0, MP0} ----------------
__global__ __launch_bounds__(256) void k_dots() {
    __shared__ float ap_s[16 * 512];
    int bt0 = blockIdx.x * 16, tid = threadIdx.x;
    for (int i = tid; i < 16 * 512; i += 256) ap_s[i] = g_AP0[bt0 * 512 + i];
    __syncthreads();
    for (int o = tid; o < 16 * 192; o += 256) {
        int row = o / 192, col = o % 192;
        const float4* v = (col < 128) ? (const float4*)(g_CB0 + col * 512)
                                      : (const float4*)(g_MP0 + (col - 128) * 512);
        const float4* a = (const float4*)(ap_s + row * 512);
        float d = 0.f;
#pragma unroll 8
        for (int i = 0; i < 128; i++) {
            float4 x = a[i], y = v[i];
            d += x.x * y.x + x.y * y.y + x.z * y.z + x.w * y.w;
        }
        if (col < 128) g_dapcb[(bt0 + row) * 128 + col] = d;
        else           g_dapmp[(bt0 + row) * 64 + col - 128] = d;
    }
}

// ---------------- kernel: pack W1 into mma-fragment order, fp16 ----------------
__global__ __launch_bounds__(256) void k_wt(const float* __restrict__ W1) {
    int idx = blockIdx.x * 256 + threadIdx.x;     // 32768 total
    int r    = idx & 1;
    int lane = (idx >> 1) & 31;
    int nf   = (idx >> 6) & 15;
    int s    = (idx >> 10) & 7;
    int c    = (idx >> 13) & 3;
    int k_loc = s * 16 + (lane & 3) * 2 + r * 8;
    int col   = nf * 8 + (lane >> 2);
    int kg    = c * 128 + k_loc;
    float v0 = W1[kg * 128 + col];
    float v1 = W1[(kg + 1) * 128 + col];
    __half2 hp = __floats2half2_rn(v0, v1);
    g_Wf[(((c * 8 + s) * 16 + nf) * 32 + lane) * 2 + r] = *(uint32_t*)&hp;
}

// ---------------- main kernel ----------------
// grid 4096 (2 bt = 128 rows each), 256 threads = 8 warps, 2 CTAs/SM
#define SOFF_HHI  0
#define SOFF_HLO  32768
#define SOFF_B    65536
#define SOFF_AP   98304
#define SOFF_GS   102400
#define SOFF_TS   104448
#define SOFF_LAT  106496
#define SOFF_MEAN 107008
#define SOFF_RS   107520
#define SOFF_B1   108032
#define SMEM_BYTES 108544

__global__ __launch_bounds__(256, 2) void k_main(
    const int* __restrict__ lat_idx,
    const float* __restrict__ b1,
    const float* __restrict__ g0, const float* __restrict__ t0,
    float* __restrict__ out)
{
    extern __shared__ char smem[];
    float* ap_s   = (float*)(smem + SOFF_AP);
    float* gs_s   = (float*)(smem + SOFF_GS);
    float* ts_s   = (float*)(smem + SOFF_TS);
    int*   lat_s  = (int*)(smem + SOFF_LAT);
    float* mean_s = (float*)(smem + SOFF_MEAN);
    float* rs_s   = (float*)(smem + SOFF_RS);
    float* b1_s   = (float*)(smem + SOFF_B1);
    uint2* B2     = (uint2*)(smem + SOFF_B);

    int tid = threadIdx.x, wid = tid >> 5, lane = tid & 31;
    int p = blockIdx.x;

    for (int i = tid; i < 1024; i += 256) ap_s[i] = g_AP0[p * 1024 + i];
    for (int i = tid; i < 512; i += 256) { gs_s[i] = g0[i]; ts_s[i] = t0[i]; }
    if (tid < 128) {
        int lat = lat_idx[p * 128 + tid];
        lat_s[tid] = lat;
        b1_s[tid] = b1[tid];
        // LN stats from precomputed sums + cross dots
        int m = tid & 63;
        int btg = p * 2 + (tid >> 6);
        float sum = g_scb[lat] + g_smp[m] + g_sap[btg];
        float ssq = g_qcb[lat] + g_qmp[m] + g_qap[btg]
                  + 2.f * (g_dcm[lat * 64 + m] + g_dapcb[btg * 128 + lat] + g_dapmp[btg * 64 + m]);
        float mean = sum * (1.f / 512.f);
        float var = ssq * (1.f / 512.f) - mean * mean;
        mean_s[tid] = mean;
        rs_s[tid] = rsqrtf(var + LN_EPS);
    }
    __syncthreads();

    // warp tiling
    int rg = wid >> 1, cg = wid & 1;
    int R = rg * 32;
    int mat = lane >> 3, rl = lane & 7;
    int rowA0 = R + ((mat & 1) << 3) + rl;
    uint32_t sbH = smem_u32(smem) + SOFF_HHI;
    uint32_t sbL = smem_u32(smem) + SOFF_HLO;

    float acc0[8][4], acc1[8][4];
#pragma unroll
    for (int nf = 0; nf < 8; nf++)
#pragma unroll
        for (int i = 0; i < 4; i++) { acc0[nf][i] = 0.f; acc1[nf][i] = 0.f; }

    int rowB = tid & 127;
    int gH = tid >> 7;
    const float* cbp = g_CB0 + lat_s[rowB] * 512;
    const float* mpp = g_MP0 + (rowB & 63) * 512;
    const float* app = ap_s + (rowB >> 6) * 512;

    for (int c = 0; c < 4; c++) {
        // ---- copy W frag chunk (32KB) ----
        {
            const uint4* src = (const uint4*)(g_Wf + c * 8192);
            uint4* dst = (uint4*)(smem + SOFF_B);
#pragma unroll
            for (int i = 0; i < 8; i++) dst[i * 256 + tid] = src[i * 256 + tid];
        }
        // ---- build H chunk hi/lo fp16 tiles ----
        {
            float mean = mean_s[rowB], rsv = rs_s[rowB];
#pragma unroll
            for (int ul = 0; ul < 8; ul++) {
                int u = gH * 8 + ul;
                int kg = c * 128 + u * 8;
                float4 A0 = *(const float4*)(cbp + kg);
                float4 A1 = *(const float4*)(cbp + kg + 4);
                float4 B0 = *(const float4*)(mpp + kg);
                float4 B1 = *(const float4*)(mpp + kg + 4);
                float4 E0 = *(const float4*)(app + kg);
                float4 E1 = *(const float4*)(app + kg + 4);
                float4 G0 = *(const float4*)(gs_s + kg);
                float4 G1 = *(const float4*)(gs_s + kg + 4);
                float4 T0 = *(const float4*)(ts_s + kg);
                float4 T1 = *(const float4*)(ts_s + kg + 4);
                float h[8];
                h[0] = fmaxf(fmaf((A0.x + B0.x + E0.x - mean) * rsv, G0.x, T0.x), 0.f);
                h[1] = fmaxf(fmaf((A0.y + B0.y + E0.y - mean) * rsv, G0.y, T0.y), 0.f);
                h[2] = fmaxf(fmaf((A0.z + B0.z + E0.z - mean) * rsv, G0.z, T0.z), 0.f);
                h[3] = fmaxf(fmaf((A0.w + B0.w + E0.w - mean) * rsv, G0.w, T0.w), 0.f);
                h[4] = fmaxf(fmaf((A1.x + B1.x + E1.x - mean) * rsv, G1.x, T1.x), 0.f);
                h[5] = fmaxf(fmaf((A1.y + B1.y + E1.y - mean) * rsv, G1.y, T1.y), 0.f);
                h[6] = fmaxf(fmaf((A1.z + B1.z + E1.z - mean) * rsv, G1.z, T1.z), 0.f);
                h[7] = fmaxf(fmaf((A1.w + B1.w + E1.w - mean) * rsv, G1.w, T1.w), 0.f);
                __half hh[8];
                float lo[8];
#pragma unroll
                for (int i = 0; i < 8; i++) {
                    hh[i] = __float2half_rn(h[i]);
                    lo[i] = h[i] - __half2float(hh[i]);
                }
                uint4 hv, lv;
                __half2 hp0 = __halves2half2(hh[0], hh[1]);
                __half2 hp1 = __halves2half2(hh[2], hh[3]);
                __half2 hp2 = __halves2half2(hh[4], hh[5]);
                __half2 hp3 = __halves2half2(hh[6], hh[7]);
                hv.x = *(uint32_t*)&hp0; hv.y = *(uint32_t*)&hp1;
                hv.z = *(uint32_t*)&hp2; hv.w = *(uint32_t*)&hp3;
                __half2 lp0 = __floats2half2_rn(lo[0], lo[1]);
                __half2 lp1 = __floats2half2_rn(lo[2], lo[3]);
                __half2 lp2 = __floats2half2_rn(lo[4], lo[5]);
                __half2 lp3 = __floats2half2_rn(lo[6], lo[7]);
                lv.x = *(uint32_t*)&lp0; lv.y = *(uint32_t*)&lp1;
                lv.z = *(uint32_t*)&lp2; lv.w = *(uint32_t*)&lp3;
                uint32_t sw = (uint32_t)rowB * 256 + (uint32_t)((u ^ (rowB & 7)) << 4);
                *(uint4*)(smem + SOFF_HHI + sw) = hv;
                *(uint4*)(smem + SOFF_HLO + sw) = lv;
            }
        }
        __syncthreads();

        // ---- mma over this chunk: 2-pass (H = hi + lo), W single plane ----
#pragma unroll
        for (int s = 0; s < 8; s++) {
            uint32_t ah0[4], ah1[4], al0[4], al1[4];
            int u0 = s * 2 + (mat >> 1);
            int r0 = rowA0, r1 = rowA0 + 16;
            uint32_t off0 = (uint32_t)r0 * 256 + (uint32_t)((u0 ^ (r0 & 7)) << 4);
            uint32_t off1 = (uint32_t)r1 * 256 + (uint32_t)((u0 ^ (r1 & 7)) << 4);
            ldsm4(ah0, sbH + off0);
            ldsm4(ah1, sbH + off1);
            ldsm4(al0, sbL + off0);
            ldsm4(al1, sbL + off1);
#pragma unroll
            for (int nf = 0; nf < 8; nf++) {
                int nfg = cg * 8 + nf;
                uint2 bw = B2[(s * 16 + nfg) * 32 + lane];
                mma_f16(acc0[nf], ah0, bw);
                mma_f16(acc1[nf], ah1, bw);
                mma_f16(acc0[nf], al0, bw);
                mma_f16(acc1[nf], al1, bw);
            }
        }
        __syncthreads();
    }

    // ---- epilogue ----
    {
        int r0 = R + (lane >> 2);
        int colb = cg * 64 + (lane & 3) * 2;
        long rowg = (long)p * 128;
#pragma unroll
        for (int nf = 0; nf < 8; nf++) {
            int col = colb + nf * 8;
            float ba = b1_s[col], bb = b1_s[col + 1];
            float* o0 = out + (rowg + r0) * 128 + col;
            *(float2*)o0 = make_float2(acc0[nf][0] + ba, acc0[nf][1] + bb);
            *(float2*)(o0 + 8 * 128) = make_float2(acc0[nf][2] + ba, acc0[nf][3] + bb);
            float* o1 = out + (rowg + r0 + 16) * 128 + col;
            *(float2*)o1 = make_float2(acc1[nf][0] + ba, acc1[nf][1] + bb);
            *(float2*)(o1 + 8 * 128) = make_float2(acc1[nf][2] + ba, acc1[nf][3] + bb);
        }
    }
}

// ---------------- launch ----------------
extern "C" void kernel_launch(void* const* d_in, const int* in_sizes, int n_in,
                              void* d_out, int out_size) {
    const int*   map_latent = (const int*)d_in[0];
    const float* heading    = (const float*)d_in[1];
    const float* position   = (const float*)d_in[2];
    const float* tokenizer  = (const float*)d_in[3];
    const float* mpl        = (const float*)d_in[4];
    const float* ape_w0 = (const float*)d_in[5];
    const float* ape_b0 = (const float*)d_in[6];
    const float* ape_g0 = (const float*)d_in[7];
    const float* ape_t0 = (const float*)d_in[8];
    const float* ape_w1 = (const float*)d_in[9];
    const float* ape_b1 = (const float*)d_in[10];
    const float* ape_g1 = (const float*)d_in[11];
    const float* ape_t1 = (const float*)d_in[12];
    const float* ape_w2 = (const float*)d_in[13];
    const float* ape_b2 = (const float*)d_in[14];
    const float* mla_w0 = (const float*)d_in[15];
    const float* mla_b0 = (const float*)d_in[16];
    const float* mla_g0 = (const float*)d_in[17];
    const float* mla_t0 = (const float*)d_in[18];
    const float* mla_w1 = (const float*)d_in[19];
    const float* mla_b1 = (const float*)d_in[20];
    const float* mpm_w0 = (const float*)d_in[21];
    const float* mpm_b0 = (const float*)d_in[22];
    const float* mpm_g0 = (const float*)d_in[23];
    const float* mpm_t0 = (const float*)d_in[24];
    const float* mpm_w1 = (const float*)d_in[25];
    const float* mpm_b1 = (const float*)d_in[26];
    float* out = (float*)d_out;

    cudaFuncSetAttribute(k_main, cudaFuncAttributeMaxDynamicSharedMemorySize, SMEM_BYTES);

    k_mp<<<64, 128>>>(mpl, mpm_w0, mpm_b0, mpm_g0, mpm_t0, mpm_w1, mpm_b1, mla_w0);
    k_cb<<<128, 128>>>(tokenizer, mla_w0);
    k_dcm<<<64, 128>>>();
    k_wt<<<128, 256>>>(mla_w1);
    k_ape4<<<2048, 128>>>(heading, position,
                          ape_w0, ape_b0, ape_g0, ape_t0,
                          ape_w1, ape_b1, ape_g1, ape_t1,
                          ape_w2, ape_b2, mla_w0, mla_b0);
    k_dots<<<512, 256>>>();
    k_main<<<4096, 256, SMEM_BYTES>>>(map_latent, mla_b1, mla_g0, mla_t0, out);
}

// round 11
// speedup vs baseline: 1.1179x; 1.1179x over previous
#include <cuda_runtime.h>
#include <cuda_fp16.h>
#include <cstdint>
#include <math.h>

#define LN_EPS 1e-5f

// ---------------- device scratch ----------------
__device__ float g_CB0[128 * 512];      // codebook @ mla_w0
__device__ float g_MP0[64 * 512];       // map_pos_embed @ mla_w0
__device__ float g_AP0[8192 * 512];     // agent_pos_embed @ mla_w0 + mla_b0
__device__ uint32_t g_Wf[32768];        // W1 frag-packed fp16: [c4][s8][nf16][lane32][r2]

// ---------------- helpers ----------------
__device__ __forceinline__ uint32_t smem_u32(const void* p) {
    uint32_t a;
    asm("{ .reg .u64 t; cvta.to.shared.u64 t, %1; cvt.u32.u64 %0, t; }" : "=r"(a) : "l"(p));
    return a;
}
__device__ __forceinline__ void ldsm4(uint32_t (&r)[4], uint32_t addr) {
    asm volatile("ldmatrix.sync.aligned.m8n8.x4.shared.b16 {%0,%1,%2,%3}, [%4];"
        : "=r"(r[0]), "=r"(r[1]), "=r"(r[2]), "=r"(r[3]) : "r"(addr));
}
__device__ __forceinline__ void mma_f16(float (&d)[4], const uint32_t (&a)[4], uint2 b) {
    asm volatile("mma.sync.aligned.m16n8k16.row.col.f32.f16.f16.f32 "
        "{%0,%1,%2,%3}, {%4,%5,%6,%7}, {%8,%9}, {%0,%1,%2,%3};"
        : "+f"(d[0]), "+f"(d[1]), "+f"(d[2]), "+f"(d[3])
        : "r"(a[0]), "r"(a[1]), "r"(a[2]), "r"(a[3]), "r"(b.x), "r"(b.y));
}
__device__ __forceinline__ void blockReduce2_128(float& s, float& s2, float* red) {
#pragma unroll
    for (int off = 16; off > 0; off >>= 1) {
        s  += __shfl_xor_sync(0xffffffffu, s,  off);
        s2 += __shfl_xor_sync(0xffffffffu, s2, off);
    }
    int w = threadIdx.x >> 5;
    if ((threadIdx.x & 31) == 0) { red[w] = s; red[4 + w] = s2; }
    __syncthreads();
    s  = red[0] + red[1] + red[2] + red[3];
    s2 = red[4] + red[5] + red[6] + red[7];
    __syncthreads();
}

// ---------------- kernel: map_pos_embed MLP + projection (verified) ----------------
__global__ __launch_bounds__(128) void k_mp(
    const float* __restrict__ mpl,
    const float* __restrict__ w0, const float* __restrict__ b0,
    const float* __restrict__ g0, const float* __restrict__ t0,
    const float* __restrict__ w1, const float* __restrict__ b1,
    const float* __restrict__ W0mla)
{
    __shared__ float xs[256], hs[128], mp[128], red[8];
    int m = blockIdx.x, j = threadIdx.x;
    xs[j] = mpl[m * 256 + j];
    xs[128 + j] = mpl[m * 256 + 128 + j];
    __syncthreads();

    float z = b0[j];
#pragma unroll 8
    for (int i = 0; i < 256; i++) z = fmaf(xs[i], w0[i * 128 + j], z);
    float s = z, s2 = z * z;
    blockReduce2_128(s, s2, red);
    float mean = s * (1.f / 128.f);
    float var = s2 * (1.f / 128.f) - mean * mean;
    float rs = rsqrtf(var + LN_EPS);
    hs[j] = fmaxf((z - mean) * rs * g0[j] + t0[j], 0.f);
    __syncthreads();

    float z1 = b1[j];
#pragma unroll 8
    for (int i = 0; i < 128; i++) z1 = fmaf(hs[i], w1[i * 128 + j], z1);
    mp[j] = z1;
    __syncthreads();

#pragma unroll
    for (int q = 0; q < 4; q++) {
        int c = j + q * 128;
        float acc = 0.f;
#pragma unroll 8
        for (int i = 0; i < 128; i++) acc = fmaf(mp[i], W0mla[i * 512 + c], acc);
        g_MP0[m * 512 + c] = acc;
    }
}

// ---------------- kernel: codebook @ mla_w0 (verified) ----------------
__global__ __launch_bounds__(128) void k_cb(
    const float* __restrict__ tok, const float* __restrict__ W0mla)
{
    __shared__ float cb[128];
    int lat = blockIdx.x, j = threadIdx.x;
    cb[j] = tok[lat * 128 + j];
    __syncthreads();
#pragma unroll
    for (int q = 0; q < 4; q++) {
        int c = j + q * 128;
        float acc = 0.f;
#pragma unroll 8
        for (int i = 0; i < 128; i++) acc = fmaf(cb[i], W0mla[i * 512 + c], acc);
        g_CB0[lat * 512 + c] = acc;
    }
}

// ---------------- kernel: agent_pos_emb MLP + projection (verified, 160us) ----------------
__global__ __launch_bounds__(128) void k_ape(
    const float* __restrict__ heading, const float* __restrict__ position,
    const float* __restrict__ w0, const float* __restrict__ b0,
    const float* __restrict__ g0, const float* __restrict__ t0,
    const float* __restrict__ w1, const float* __restrict__ b1,
    const float* __restrict__ g1, const float* __restrict__ t1,
    const float* __restrict__ w2, const float* __restrict__ b2,
    const float* __restrict__ W0mla, const float* __restrict__ b0mla)
{
    __shared__ float a1[128], a2[128], av[128], red[8];
    int bt = blockIdx.x;
    int b = bt >> 7, t = bt & 127;
    int j = threadIdx.x;

    float hd = heading[(b * 32) * 128 + t];
    float px = position[((b * 32) * 128 + t) * 2 + 0];
    float py = position[((b * 32) * 128 + t) * 2 + 1];
    float sh = sinf(hd), ch = cosf(hd);

    float z = b0[j];
    z = fmaf(px, w0[0 * 128 + j], z);
    z = fmaf(py, w0[1 * 128 + j], z);
    z = fmaf(hd, w0[2 * 128 + j], z);
    z = fmaf(sh, w0[3 * 128 + j], z);
    z = fmaf(ch, w0[4 * 128 + j], z);
    float s = z, s2 = z * z;
    blockReduce2_128(s, s2, red);
    float mean = s * (1.f / 128.f);
    float var = s2 * (1.f / 128.f) - mean * mean;
    float rs = rsqrtf(var + LN_EPS);
    a1[j] = fmaxf((z - mean) * rs * g0[j] + t0[j], 0.f);
    __syncthreads();

    float z1 = b1[j];
#pragma unroll 8
    for (int i = 0; i < 128; i++) z1 = fmaf(a1[i], w1[i * 128 + j], z1);
    s = z1; s2 = z1 * z1;
    blockReduce2_128(s, s2, red);
    mean = s * (1.f / 128.f);
    var = s2 * (1.f / 128.f) - mean * mean;
    rs = rsqrtf(var + LN_EPS);
    a2[j] = fmaxf((z1 - mean) * rs * g1[j] + t1[j], 0.f);
    __syncthreads();

    float z2 = b2[j];
#pragma unroll 8
    for (int i = 0; i < 128; i++) z2 = fmaf(a2[i], w2[i * 128 + j], z2);
    av[j] = z2;
    __syncthreads();

#pragma unroll
    for (int q = 0; q < 4; q++) {
        int c = j + q * 128;
        float acc = b0mla[c];
#pragma unroll 8
        for (int i = 0; i < 128; i++) acc = fmaf(av[i], W0mla[i * 512 + c], acc);
        g_AP0[bt * 512 + c] = acc;
    }
}

// ---------------- kernel: pack W1 into mma-fragment order, fp16 ----------------
__global__ __launch_bounds__(256) void k_wt(const float* __restrict__ W1) {
    int idx = blockIdx.x * 256 + threadIdx.x;     // 32768 total
    int r    = idx & 1;
    int lane = (idx >> 1) & 31;
    int nf   = (idx >> 6) & 15;
    int s    = (idx >> 10) & 7;
    int c    = (idx >> 13) & 3;
    int k_loc = s * 16 + (lane & 3) * 2 + r * 8;
    int col   = nf * 8 + (lane >> 2);
    int kg    = c * 128 + k_loc;
    float v0 = W1[kg * 128 + col];
    float v1 = W1[(kg + 1) * 128 + col];
    __half2 hp = __floats2half2_rn(v0, v1);
    g_Wf[(((c * 8 + s) * 16 + nf) * 32 + lane) * 2 + r] = *(uint32_t*)&hp;
}

// ---------------- main kernel: gather + LN(stats pre-pass) + HMMA fp16 2-pass ----------------
// grid 4096 (2 bt = 128 rows each), 256 threads = 8 warps, 2 CTAs/SM
#define SOFF_HHI  0
#define SOFF_HLO  32768
#define SOFF_B    65536
#define SOFF_AP   98304
#define SOFF_GS   102400
#define SOFF_TS   104448
#define SOFF_LAT  106496
#define SOFF_MEAN 107008
#define SOFF_RS   107520
#define SOFF_B1   108032
#define SMEM_BYTES 108544

__global__ __launch_bounds__(256, 2) void k_main(
    const int* __restrict__ lat_idx,
    const float* __restrict__ b1,
    const float* __restrict__ g0, const float* __restrict__ t0,
    float* __restrict__ out)
{
    extern __shared__ char smem[];
    float* ap_s   = (float*)(smem + SOFF_AP);
    float* gs_s   = (float*)(smem + SOFF_GS);
    float* ts_s   = (float*)(smem + SOFF_TS);
    int*   lat_s  = (int*)(smem + SOFF_LAT);
    float* mean_s = (float*)(smem + SOFF_MEAN);
    float* rs_s   = (float*)(smem + SOFF_RS);
    float* b1_s   = (float*)(smem + SOFF_B1);
    uint2* B2     = (uint2*)(smem + SOFF_B);

    int tid = threadIdx.x, wid = tid >> 5, lane = tid & 31;
    int p = blockIdx.x;

    for (int i = tid; i < 1024; i += 256) ap_s[i] = g_AP0[p * 1024 + i];
    for (int i = tid; i < 512; i += 256) { gs_s[i] = g0[i]; ts_s[i] = t0[i]; }
    if (tid < 128) {
        lat_s[tid] = lat_idx[p * 128 + tid];
        b1_s[tid] = b1[tid];
    }
    __syncthreads();

    // ---- LN stats pre-pass: row = tid>>1, half = tid&1 ----
    {
        int r = tid >> 1, ht = tid & 1;
        const float4* c4 = (const float4*)(g_CB0 + lat_s[r] * 512 + ht * 256);
        const float4* m4 = (const float4*)(g_MP0 + (r & 63) * 512 + ht * 256);
        const float4* a4 = (const float4*)(ap_s + (r >> 6) * 512 + ht * 256);
        float s = 0.f, s2 = 0.f;
#pragma unroll 8
        for (int i = 0; i < 64; i++) {
            float4 a = c4[i], b = m4[i], e = a4[i];
            float x0 = a.x + b.x + e.x, x1 = a.y + b.y + e.y;
            float x2 = a.z + b.z + e.z, x3 = a.w + b.w + e.w;
            s += x0 + x1 + x2 + x3;
            s2 += x0 * x0 + x1 * x1 + x2 * x2 + x3 * x3;
        }
        s += __shfl_xor_sync(0xffffffffu, s, 1);
        s2 += __shfl_xor_sync(0xffffffffu, s2, 1);
        if (ht == 0) {
            float mean = s * (1.f / 512.f);
            float var = s2 * (1.f / 512.f) - mean * mean;
            mean_s[r] = mean;
            rs_s[r] = rsqrtf(var + LN_EPS);
        }
    }
    __syncthreads();

    // warp tiling: 4 row-groups x 2 col-groups
    int rg = wid >> 1, cg = wid & 1;
    int R = rg * 32;
    int mat = lane >> 3, rl = lane & 7;
    int rowA0 = R + ((mat & 1) << 3) + rl;
    uint32_t sbH = smem_u32(smem) + SOFF_HHI;
    uint32_t sbL = smem_u32(smem) + SOFF_HLO;

    float acc0[8][4], acc1[8][4];
#pragma unroll
    for (int nf = 0; nf < 8; nf++)
#pragma unroll
        for (int i = 0; i < 4; i++) { acc0[nf][i] = 0.f; acc1[nf][i] = 0.f; }

    int rowB = tid & 127;
    int gH = tid >> 7;
    const float* cbp = g_CB0 + lat_s[rowB] * 512;
    const float* mpp = g_MP0 + (rowB & 63) * 512;
    const float* app = ap_s + (rowB >> 6) * 512;

    for (int c = 0; c < 4; c++) {
        // ---- copy W frag chunk (32KB) ----
        {
            const uint4* src = (const uint4*)(g_Wf + c * 8192);
            uint4* dst = (uint4*)(smem + SOFF_B);
#pragma unroll
            for (int i = 0; i < 8; i++) dst[i * 256 + tid] = src[i * 256 + tid];
        }
        // ---- build H chunk hi/lo fp16 tiles (swizzled for ldmatrix) ----
        {
            float mean = mean_s[rowB], rsv = rs_s[rowB];
#pragma unroll
            for (int ul = 0; ul < 8; ul++) {
                int u = gH * 8 + ul;
                int kg = c * 128 + u * 8;
                float4 A0 = *(const float4*)(cbp + kg);
                float4 A1 = *(const float4*)(cbp + kg + 4);
                float4 B0 = *(const float4*)(mpp + kg);
                float4 B1 = *(const float4*)(mpp + kg + 4);
                float4 E0 = *(const float4*)(app + kg);
                float4 E1 = *(const float4*)(app + kg + 4);
                float4 G0 = *(const float4*)(gs_s + kg);
                float4 G1 = *(const float4*)(gs_s + kg + 4);
                float4 T0 = *(const float4*)(ts_s + kg);
                float4 T1 = *(const float4*)(ts_s + kg + 4);
                float h[8];
                h[0] = fmaxf(fmaf((A0.x + B0.x + E0.x - mean) * rsv, G0.x, T0.x), 0.f);
                h[1] = fmaxf(fmaf((A0.y + B0.y + E0.y - mean) * rsv, G0.y, T0.y), 0.f);
                h[2] = fmaxf(fmaf((A0.z + B0.z + E0.z - mean) * rsv, G0.z, T0.z), 0.f);
                h[3] = fmaxf(fmaf((A0.w + B0.w + E0.w - mean) * rsv, G0.w, T0.w), 0.f);
                h[4] = fmaxf(fmaf((A1.x + B1.x + E1.x - mean) * rsv, G1.x, T1.x), 0.f);
                h[5] = fmaxf(fmaf((A1.y + B1.y + E1.y - mean) * rsv, G1.y, T1.y), 0.f);
                h[6] = fmaxf(fmaf((A1.z + B1.z + E1.z - mean) * rsv, G1.z, T1.z), 0.f);
                h[7] = fmaxf(fmaf((A1.w + B1.w + E1.w - mean) * rsv, G1.w, T1.w), 0.f);
                __half hh[8];
                float lo[8];
#pragma unroll
                for (int i = 0; i < 8; i++) {
                    hh[i] = __float2half_rn(h[i]);
                    lo[i] = h[i] - __half2float(hh[i]);
                }
                uint4 hv, lv;
                __half2 hp0 = __halves2half2(hh[0], hh[1]);
                __half2 hp1 = __halves2half2(hh[2], hh[3]);
                __half2 hp2 = __halves2half2(hh[4], hh[5]);
                __half2 hp3 = __halves2half2(hh[6], hh[7]);
                hv.x = *(uint32_t*)&hp0; hv.y = *(uint32_t*)&hp1;
                hv.z = *(uint32_t*)&hp2; hv.w = *(uint32_t*)&hp3;
                __half2 lp0 = __floats2half2_rn(lo[0], lo[1]);
                __half2 lp1 = __floats2half2_rn(lo[2], lo[3]);
                __half2 lp2 = __floats2half2_rn(lo[4], lo[5]);
                __half2 lp3 = __floats2half2_rn(lo[6], lo[7]);
                lv.x = *(uint32_t*)&lp0; lv.y = *(uint32_t*)&lp1;
                lv.z = *(uint32_t*)&lp2; lv.w = *(uint32_t*)&lp3;
                uint32_t sw = (uint32_t)rowB * 256 + (uint32_t)((u ^ (rowB & 7)) << 4);
                *(uint4*)(smem + SOFF_HHI + sw) = hv;
                *(uint4*)(smem + SOFF_HLO + sw) = lv;
            }
        }
        __syncthreads();

        // ---- mma: 2-pass (H = hi + lo), single W plane ----
#pragma unroll
        for (int s = 0; s < 8; s++) {
            uint32_t ah0[4], ah1[4], al0[4], al1[4];
            int u0 = s * 2 + (mat >> 1);
            int r0 = rowA0, r1 = rowA0 + 16;
            uint32_t off0 = (uint32_t)r0 * 256 + (uint32_t)((u0 ^ (r0 & 7)) << 4);
            uint32_t off1 = (uint32_t)r1 * 256 + (uint32_t)((u0 ^ (r1 & 7)) << 4);
            ldsm4(ah0, sbH + off0);
            ldsm4(ah1, sbH + off1);
            ldsm4(al0, sbL + off0);
            ldsm4(al1, sbL + off1);
#pragma unroll
            for (int nf = 0; nf < 8; nf++) {
                int nfg = cg * 8 + nf;
                uint2 bw = B2[(s * 16 + nfg) * 32 + lane];
                mma_f16(acc0[nf], ah0, bw);
                mma_f16(acc1[nf], ah1, bw);
                mma_f16(acc0[nf], al0, bw);
                mma_f16(acc1[nf], al1, bw);
            }
        }
        __syncthreads();
    }

    // ---- epilogue ----
    {
        int r0 = R + (lane >> 2);
        int colb = cg * 64 + (lane & 3) * 2;
        long rowg = (long)p * 128;
#pragma unroll
        for (int nf = 0; nf < 8; nf++) {
            int col = colb + nf * 8;
            float ba = b1_s[col], bb = b1_s[col + 1];
            float* o0 = out + (rowg + r0) * 128 + col;
            *(float2*)o0 = make_float2(acc0[nf][0] + ba, acc0[nf][1] + bb);
            *(float2*)(o0 + 8 * 128) = make_float2(acc0[nf][2] + ba, acc0[nf][3] + bb);
            float* o1 = out + (rowg + r0 + 16) * 128 + col;
            *(float2*)o1 = make_float2(acc1[nf][0] + ba, acc1[nf][1] + bb);
            *(float2*)(o1 + 8 * 128) = make_float2(acc1[nf][2] + ba, acc1[nf][3] + bb);
        }
    }
}

// ---------------- launch ----------------
extern "C" void kernel_launch(void* const* d_in, const int* in_sizes, int n_in,
                              void* d_out, int out_size) {
    const int*   map_latent = (const int*)d_in[0];
    const float* heading    = (const float*)d_in[1];
    const float* position   = (const float*)d_in[2];
    const float* tokenizer  = (const float*)d_in[3];
    const float* mpl        = (const float*)d_in[4];
    const float* ape_w0 = (const float*)d_in[5];
    const float* ape_b0 = (const float*)d_in[6];
    const float* ape_g0 = (const float*)d_in[7];
    const float* ape_t0 = (const float*)d_in[8];
    const float* ape_w1 = (const float*)d_in[9];
    const float* ape_b1 = (const float*)d_in[10];
    const float* ape_g1 = (const float*)d_in[11];
    const float* ape_t1 = (const float*)d_in[12];
    const float* ape_w2 = (const float*)d_in[13];
    const float* ape_b2 = (const float*)d_in[14];
    const float* mla_w0 = (const float*)d_in[15];
    const float* mla_b0 = (const float*)d_in[16];
    const float* mla_g0 = (const float*)d_in[17];
    const float* mla_t0 = (const float*)d_in[18];
    const float* mla_w1 = (const float*)d_in[19];
    const float* mla_b1 = (const float*)d_in[20];
    const float* mpm_w0 = (const float*)d_in[21];
    const float* mpm_b0 = (const float*)d_in[22];
    const float* mpm_g0 = (const float*)d_in[23];
    const float* mpm_t0 = (const float*)d_in[24];
    const float* mpm_w1 = (const float*)d_in[25];
    const float* mpm_b1 = (const float*)d_in[26];
    float* out = (float*)d_out;

    cudaFuncSetAttribute(k_main, cudaFuncAttributeMaxDynamicSharedMemorySize, SMEM_BYTES);

    k_mp<<<64, 128>>>(mpl, mpm_w0, mpm_b0, mpm_g0, mpm_t0, mpm_w1, mpm_b1, mla_w0);
    k_cb<<<128, 128>>>(tokenizer, mla_w0);
    k_wt<<<128, 256>>>(mla_w1);
    k_ape<<<8192, 128>>>(heading, position,
                         ape_w0, ape_b0, ape_g0, ape_t0,
                         ape_w1, ape_b1, ape_g1, ape_t1,
                         ape_w2, ape_b2, mla_w0, mla_b0);
    k_main<<<4096, 256, SMEM_BYTES>>>(map_latent, mla_b1, mla_g0, mla_t0, out);
}

// round 15
// speedup vs baseline: 2.0414x; 1.8261x over previous
#include <cuda_runtime.h>
#include <cuda_fp16.h>
#include <cstdint>
#include <math.h>

#define LN_EPS 1e-5f

// ---------------- device scratch ----------------
__device__ float g_CB0[128 * 512];      // codebook @ mla_w0
__device__ float g_MP0[64 * 512];       // map_pos_embed @ mla_w0
__device__ float g_AP0[8192 * 512];     // agent_pos_embed @ mla_w0 + mla_b0
__device__ uint32_t g_Wf[32768];        // W1 frag-packed fp16: [c4][s8][nf16][lane32][r2]

// ---------------- helpers ----------------
__device__ __forceinline__ uint32_t smem_u32(const void* p) {
    uint32_t a;
    asm("{ .reg .u64 t; cvta.to.shared.u64 t, %1; cvt.u32.u64 %0, t; }" : "=r"(a) : "l"(p));
    return a;
}
__device__ __forceinline__ void ldsm4(uint32_t (&r)[4], uint32_t addr) {
    asm volatile("ldmatrix.sync.aligned.m8n8.x4.shared.b16 {%0,%1,%2,%3}, [%4];"
        : "=r"(r[0]), "=r"(r[1]), "=r"(r[2]), "=r"(r[3]) : "r"(addr));
}
__device__ __forceinline__ void mma_f16(float (&d)[4], const uint32_t (&a)[4], uint2 b) {
    asm volatile("mma.sync.aligned.m16n8k16.row.col.f32.f16.f16.f32 "
        "{%0,%1,%2,%3}, {%4,%5,%6,%7}, {%8,%9}, {%0,%1,%2,%3};"
        : "+f"(d[0]), "+f"(d[1]), "+f"(d[2]), "+f"(d[3])
        : "r"(a[0]), "r"(a[1]), "r"(a[2]), "r"(a[3]), "r"(b.x), "r"(b.y));
}
__device__ __forceinline__ void blockReduce2_128(float& s, float& s2, float* red) {
#pragma unroll
    for (int off = 16; off > 0; off >>= 1) {
        s  += __shfl_xor_sync(0xffffffffu, s,  off);
        s2 += __shfl_xor_sync(0xffffffffu, s2, off);
    }
    int w = threadIdx.x >> 5;
    if ((threadIdx.x & 31) == 0) { red[w] = s; red[4 + w] = s2; }
    __syncthreads();
    s  = red[0] + red[1] + red[2] + red[3];
    s2 = red[4] + red[5] + red[6] + red[7];
    __syncthreads();
}

// ---------------- kernel: map_pos_embed MLP + projection (verified) ----------------
__global__ __launch_bounds__(128) void k_mp(
    const float* __restrict__ mpl,
    const float* __restrict__ w0, const float* __restrict__ b0,
    const float* __restrict__ g0, const float* __restrict__ t0,
    const float* __restrict__ w1, const float* __restrict__ b1,
    const float* __restrict__ W0mla)
{
    __shared__ float xs[256], hs[128], mp[128], red[8];
    int m = blockIdx.x, j = threadIdx.x;
    xs[j] = mpl[m * 256 + j];
    xs[128 + j] = mpl[m * 256 + 128 + j];
    __syncthreads();

    float z = b0[j];
#pragma unroll 8
    for (int i = 0; i < 256; i++) z = fmaf(xs[i], w0[i * 128 + j], z);
    float s = z, s2 = z * z;
    blockReduce2_128(s, s2, red);
    float mean = s * (1.f / 128.f);
    float var = s2 * (1.f / 128.f) - mean * mean;
    float rs = rsqrtf(var + LN_EPS);
    hs[j] = fmaxf((z - mean) * rs * g0[j] + t0[j], 0.f);
    __syncthreads();

    float z1 = b1[j];
#pragma unroll 8
    for (int i = 0; i < 128; i++) z1 = fmaf(hs[i], w1[i * 128 + j], z1);
    mp[j] = z1;
    __syncthreads();

#pragma unroll
    for (int q = 0; q < 4; q++) {
        int c = j + q * 128;
        float acc = 0.f;
#pragma unroll 8
        for (int i = 0; i < 128; i++) acc = fmaf(mp[i], W0mla[i * 512 + c], acc);
        g_MP0[m * 512 + c] = acc;
    }
}

// ---------------- kernel: codebook @ mla_w0 (verified) ----------------
__global__ __launch_bounds__(128) void k_cb(
    const float* __restrict__ tok, const float* __restrict__ W0mla)
{
    __shared__ float cb[128];
    int lat = blockIdx.x, j = threadIdx.x;
    cb[j] = tok[lat * 128 + j];
    __syncthreads();
#pragma unroll
    for (int q = 0; q < 4; q++) {
        int c = j + q * 128;
        float acc = 0.f;
#pragma unroll 8
        for (int i = 0; i < 128; i++) acc = fmaf(cb[i], W0mla[i * 512 + c], acc);
        g_CB0[lat * 512 + c] = acc;
    }
}

// ---------------- kernel: agent_pos_emb MLP + projection (verified, 160us) ----------------
__global__ __launch_bounds__(128) void k_ape(
    const float* __restrict__ heading, const float* __restrict__ position,
    const float* __restrict__ w0, const float* __restrict__ b0,
    const float* __restrict__ g0, const float* __restrict__ t0,
    const float* __restrict__ w1, const float* __restrict__ b1,
    const float* __restrict__ g1, const float* __restrict__ t1,
    const float* __restrict__ w2, const float* __restrict__ b2,
    const float* __restrict__ W0mla, const float* __restrict__ b0mla)
{
    __shared__ float a1[128], a2[128], av[128], red[8];
    int bt = blockIdx.x;
    int b = bt >> 7, t = bt & 127;
    int j = threadIdx.x;

    float hd = heading[(b * 32) * 128 + t];
    float px = position[((b * 32) * 128 + t) * 2 + 0];
    float py = position[((b * 32) * 128 + t) * 2 + 1];
    float sh = sinf(hd), ch = cosf(hd);

    float z = b0[j];
    z = fmaf(px, w0[0 * 128 + j], z);
    z = fmaf(py, w0[1 * 128 + j], z);
    z = fmaf(hd, w0[2 * 128 + j], z);
    z = fmaf(sh, w0[3 * 128 + j], z);
    z = fmaf(ch, w0[4 * 128 + j], z);
    float s = z, s2 = z * z;
    blockReduce2_128(s, s2, red);
    float mean = s * (1.f / 128.f);
    float var = s2 * (1.f / 128.f) - mean * mean;
    float rs = rsqrtf(var + LN_EPS);
    a1[j] = fmaxf((z - mean) * rs * g0[j] + t0[j], 0.f);
    __syncthreads();

    float z1 = b1[j];
#pragma unroll 8
    for (int i = 0; i < 128; i++) z1 = fmaf(a1[i], w1[i * 128 + j], z1);
    s = z1; s2 = z1 * z1;
    blockReduce2_128(s, s2, red);
    mean = s * (1.f / 128.f);
    var = s2 * (1.f / 128.f) - mean * mean;
    rs = rsqrtf(var + LN_EPS);
    a2[j] = fmaxf((z1 - mean) * rs * g1[j] + t1[j], 0.f);
    __syncthreads();

    float z2 = b2[j];
#pragma unroll 8
    for (int i = 0; i < 128; i++) z2 = fmaf(a2[i], w2[i * 128 + j], z2);
    av[j] = z2;
    __syncthreads();

#pragma unroll
    for (int q = 0; q < 4; q++) {
        int c = j + q * 128;
        float acc = b0mla[c];
#pragma unroll 8
        for (int i = 0; i < 128; i++) acc = fmaf(av[i], W0mla[i * 512 + c], acc);
        g_AP0[bt * 512 + c] = acc;
    }
}

// ---------------- kernel: pack W1 into mma-fragment order, fp16 ----------------
__global__ __launch_bounds__(256) void k_wt(const float* __restrict__ W1) {
    int idx = blockIdx.x * 256 + threadIdx.x;     // 32768 total
    int r    = idx & 1;
    int lane = (idx >> 1) & 31;
    int nf   = (idx >> 6) & 15;
    int s    = (idx >> 10) & 7;
    int c    = (idx >> 13) & 3;
    int k_loc = s * 16 + (lane & 3) * 2 + r * 8;
    int col   = nf * 8 + (lane >> 2);
    int kg    = c * 128 + k_loc;
    float v0 = W1[kg * 128 + col];
    float v1 = W1[(kg + 1) * 128 + col];
    __half2 hp = __floats2half2_rn(v0, v1);
    g_Wf[(((c * 8 + s) * 16 + nf) * 32 + lane) * 2 + r] = *(uint32_t*)&hp;
}

// ---------------- main kernel: coalesced gather + LN + HMMA fp16 2-pass ----------------
// grid 4096 (2 bt = 128 rows each), 256 threads = 8 warps, 2 CTAs/SM
#define SOFF_HHI  0
#define SOFF_HLO  32768
#define SOFF_B    65536
#define SOFF_AP   98304
#define SOFF_GS   102400
#define SOFF_TS   104448
#define SOFF_LAT  106496
#define SOFF_MEAN 107008
#define SOFF_RS   107520
#define SOFF_B1   108032
#define SMEM_BYTES 108544

__global__ __launch_bounds__(256, 2) void k_main(
    const int* __restrict__ lat_idx,
    const float* __restrict__ b1,
    const float* __restrict__ g0, const float* __restrict__ t0,
    float* __restrict__ out)
{
    extern __shared__ char smem[];
    float* ap_s   = (float*)(smem + SOFF_AP);
    float* gs_s   = (float*)(smem + SOFF_GS);
    float* ts_s   = (float*)(smem + SOFF_TS);
    int*   lat_s  = (int*)(smem + SOFF_LAT);
    float* mean_s = (float*)(smem + SOFF_MEAN);
    float* rs_s   = (float*)(smem + SOFF_RS);
    float* b1_s   = (float*)(smem + SOFF_B1);
    uint2* B2     = (uint2*)(smem + SOFF_B);

    int tid = threadIdx.x, wid = tid >> 5, lane = tid & 31;
    int p = blockIdx.x;

    for (int i = tid; i < 1024; i += 256) ap_s[i] = g_AP0[p * 1024 + i];
    for (int i = tid; i < 512; i += 256) { gs_s[i] = g0[i]; ts_s[i] = t0[i]; }
    if (tid < 128) {
        lat_s[tid] = lat_idx[p * 128 + tid];
        b1_s[tid] = b1[tid];
    }
    __syncthreads();

    // ---- LN stats pre-pass: warp-per-row (coalesced) ----
    // warp w handles rows w*16 .. w*16+15; lanes span k.
#pragma unroll 4
    for (int rr = 0; rr < 16; rr++) {
        int r = wid * 16 + rr;
        const float4* c4 = (const float4*)(g_CB0 + lat_s[r] * 512);
        const float4* m4 = (const float4*)(g_MP0 + (r & 63) * 512);
        const float4* a4 = (const float4*)(ap_s + (r >> 6) * 512);
        float s = 0.f, s2 = 0.f;
#pragma unroll
        for (int q = 0; q < 4; q++) {
            int i = q * 32 + lane;
            float4 a = c4[i], b = m4[i], e = a4[i];
            float x0 = a.x + b.x + e.x, x1 = a.y + b.y + e.y;
            float x2 = a.z + b.z + e.z, x3 = a.w + b.w + e.w;
            s += x0 + x1 + x2 + x3;
            s2 += x0 * x0 + x1 * x1 + x2 * x2 + x3 * x3;
        }
#pragma unroll
        for (int off = 16; off > 0; off >>= 1) {
            s  += __shfl_xor_sync(0xffffffffu, s,  off);
            s2 += __shfl_xor_sync(0xffffffffu, s2, off);
        }
        if (lane == 0) {
            float mean = s * (1.f / 512.f);
            float var = s2 * (1.f / 512.f) - mean * mean;
            mean_s[r] = mean;
            rs_s[r] = rsqrtf(var + LN_EPS);
        }
    }
    __syncthreads();

    // warp tiling for mma: 4 row-groups x 2 col-groups
    int rg = wid >> 1, cg = wid & 1;
    int R = rg * 32;
    int mat = lane >> 3, rl = lane & 7;
    int rowA0 = R + ((mat & 1) << 3) + rl;
    uint32_t sbH = smem_u32(smem) + SOFF_HHI;
    uint32_t sbL = smem_u32(smem) + SOFF_HLO;

    float acc0[8][4], acc1[8][4];
#pragma unroll
    for (int nf = 0; nf < 8; nf++)
#pragma unroll
        for (int i = 0; i < 4; i++) { acc0[nf][i] = 0.f; acc1[nf][i] = 0.f; }

    // per-lane k slice for build: k = lane*4 .. lane*4+3 of each chunk
    int uB = lane >> 1;                      // 16B k-unit index
    uint32_t stsOff = (uint32_t)((lane & 1) * 8);

    for (int c = 0; c < 4; c++) {
        // ---- copy W frag chunk (32KB) ----
        {
            const uint4* src = (const uint4*)(g_Wf + c * 8192);
            uint4* dst = (uint4*)(smem + SOFF_B);
#pragma unroll
            for (int i = 0; i < 8; i++) dst[i * 256 + tid] = src[i * 256 + tid];
        }
        // ---- build H chunk: warp-per-row, lanes span k (coalesced) ----
        {
            int kg = c * 128 + lane * 4;
#pragma unroll 2
            for (int rr = 0; rr < 16; rr++) {
                int r = wid * 16 + rr;
                float4 a = *(const float4*)(g_CB0 + lat_s[r] * 512 + kg);
                float4 b = *(const float4*)(g_MP0 + (r & 63) * 512 + kg);
                float4 e = *(const float4*)(ap_s + (r >> 6) * 512 + kg);
                float4 gv = *(const float4*)(gs_s + kg);
                float4 tv = *(const float4*)(ts_s + kg);
                float mean = mean_s[r], rsv = rs_s[r];
                float h0 = fmaxf(fmaf((a.x + b.x + e.x - mean) * rsv, gv.x, tv.x), 0.f);
                float h1 = fmaxf(fmaf((a.y + b.y + e.y - mean) * rsv, gv.y, tv.y), 0.f);
                float h2 = fmaxf(fmaf((a.z + b.z + e.z - mean) * rsv, gv.z, tv.z), 0.f);
                float h3 = fmaxf(fmaf((a.w + b.w + e.w - mean) * rsv, gv.w, tv.w), 0.f);
                __half q0 = __float2half_rn(h0), q1 = __float2half_rn(h1);
                __half q2 = __float2half_rn(h2), q3 = __float2half_rn(h3);
                __half2 hp0 = __halves2half2(q0, q1);
                __half2 hp1 = __halves2half2(q2, q3);
                __half2 lp0 = __floats2half2_rn(h0 - __half2float(q0), h1 - __half2float(q1));
                __half2 lp1 = __floats2half2_rn(h2 - __half2float(q2), h3 - __half2float(q3));
                uint32_t sw = (uint32_t)r * 256 + (uint32_t)((uB ^ (r & 7)) << 4) + stsOff;
                *(uint2*)(smem + SOFF_HHI + sw) = make_uint2(*(uint32_t*)&hp0, *(uint32_t*)&hp1);
                *(uint2*)(smem + SOFF_HLO + sw) = make_uint2(*(uint32_t*)&lp0, *(uint32_t*)&lp1);
            }
        }
        __syncthreads();

        // ---- mma: 2-pass (H = hi + lo), single W plane ----
#pragma unroll
        for (int s = 0; s < 8; s++) {
            uint32_t ah0[4], ah1[4], al0[4], al1[4];
            int u0 = s * 2 + (mat >> 1);
            int r0 = rowA0, r1 = rowA0 + 16;
            uint32_t off0 = (uint32_t)r0 * 256 + (uint32_t)((u0 ^ (r0 & 7)) << 4);
            uint32_t off1 = (uint32_t)r1 * 256 + (uint32_t)((u0 ^ (r1 & 7)) << 4);
            ldsm4(ah0, sbH + off0);
            ldsm4(ah1, sbH + off1);
            ldsm4(al0, sbL + off0);
            ldsm4(al1, sbL + off1);
#pragma unroll
            for (int nf = 0; nf < 8; nf++) {
                int nfg = cg * 8 + nf;
                uint2 bw = B2[(s * 16 + nfg) * 32 + lane];
                mma_f16(acc0[nf], ah0, bw);
                mma_f16(acc1[nf], ah1, bw);
                mma_f16(acc0[nf], al0, bw);
                mma_f16(acc1[nf], al1, bw);
            }
        }
        __syncthreads();
    }

    // ---- epilogue ----
    {
        int r0 = R + (lane >> 2);
        int colb = cg * 64 + (lane & 3) * 2;
        long rowg = (long)p * 128;
#pragma unroll
        for (int nf = 0; nf < 8; nf++) {
            int col = colb + nf * 8;
            float ba = b1_s[col], bb = b1_s[col + 1];
            float* o0 = out + (rowg + r0) * 128 + col;
            *(float2*)o0 = make_float2(acc0[nf][0] + ba, acc0[nf][1] + bb);
            *(float2*)(o0 + 8 * 128) = make_float2(acc0[nf][2] + ba, acc0[nf][3] + bb);
            float* o1 = out + (rowg + r0 + 16) * 128 + col;
            *(float2*)o1 = make_float2(acc1[nf][0] + ba, acc1[nf][1] + bb);
            *(float2*)(o1 + 8 * 128) = make_float2(acc1[nf][2] + ba, acc1[nf][3] + bb);
        }
    }
}

// ---------------- launch ----------------
extern "C" void kernel_launch(void* const* d_in, const int* in_sizes, int n_in,
                              void* d_out, int out_size) {
    const int*   map_latent = (const int*)d_in[0];
    const float* heading    = (const float*)d_in[1];
    const float* position   = (const float*)d_in[2];
    const float* tokenizer  = (const float*)d_in[3];
    const float* mpl        = (const float*)d_in[4];
    const float* ape_w0 = (const float*)d_in[5];
    const float* ape_b0 = (const float*)d_in[6];
    const float* ape_g0 = (const float*)d_in[7];
    const float* ape_t0 = (const float*)d_in[8];
    const float* ape_w1 = (const float*)d_in[9];
    const float* ape_b1 = (const float*)d_in[10];
    const float* ape_g1 = (const float*)d_in[11];
    const float* ape_t1 = (const float*)d_in[12];
    const float* ape_w2 = (const float*)d_in[13];
    const float* ape_b2 = (const float*)d_in[14];
    const float* mla_w0 = (const float*)d_in[15];
    const float* mla_b0 = (const float*)d_in[16];
    const float* mla_g0 = (const float*)d_in[17];
    const float* mla_t0 = (const float*)d_in[18];
    const float* mla_w1 = (const float*)d_in[19];
    const float* mla_b1 = (const float*)d_in[20];
    const float* mpm_w0 = (const float*)d_in[21];
    const float* mpm_b0 = (const float*)d_in[22];
    const float* mpm_g0 = (const float*)d_in[23];
    const float* mpm_t0 = (const float*)d_in[24];
    const float* mpm_w1 = (const float*)d_in[25];
    const float* mpm_b1 = (const float*)d_in[26];
    float* out = (float*)d_out;

    cudaFuncSetAttribute(k_main, cudaFuncAttributeMaxDynamicSharedMemorySize, SMEM_BYTES);

    k_mp<<<64, 128>>>(mpl, mpm_w0, mpm_b0, mpm_g0, mpm_t0, mpm_w1, mpm_b1, mla_w0);
    k_cb<<<128, 128>>>(tokenizer, mla_w0);
    k_wt<<<128, 256>>>(mla_w1);
    k_ape<<<8192, 128>>>(heading, position,
                         ape_w0, ape_b0, ape_g0, ape_t0,
                         ape_w1, ape_b1, ape_g1, ape_t1,
                         ape_w2, ape_b2, mla_w0, mla_b0);
    k_main<<<4096, 256, SMEM_BYTES>>>(map_latent, mla_b1, mla_g0, mla_t0, out);
}

// round 16
// speedup vs baseline: 2.2021x; 1.0787x over previous
#include <cuda_runtime.h>
#include <cuda_fp16.h>
#include <cstdint>
#include <math.h>

#define LN_EPS 1e-5f

// ---------------- device scratch ----------------
__device__ float g_CB0[128 * 512];
__device__ float g_MP0[64 * 512];
__device__ float g_AP0[8192 * 512];
__device__ uint32_t g_Wf[32768];          // W1 frag-packed fp16
__device__ float g_scb[128], g_qcb[128];
__device__ float g_smp[64],  g_qmp[64];
__device__ float g_sap[8192], g_qap[8192];
__device__ float g_dapcb[8192 * 128];
__device__ float g_dapmp[8192 * 64];
__device__ float g_dcm[128 * 64];

// ---------------- helpers ----------------
__device__ __forceinline__ uint32_t smem_u32(const void* p) {
    uint32_t a;
    asm("{ .reg .u64 t; cvta.to.shared.u64 t, %1; cvt.u32.u64 %0, t; }" : "=r"(a) : "l"(p));
    return a;
}
__device__ __forceinline__ void ldsm4(uint32_t (&r)[4], uint32_t addr) {
    asm volatile("ldmatrix.sync.aligned.m8n8.x4.shared.b16 {%0,%1,%2,%3}, [%4];"
        : "=r"(r[0]), "=r"(r[1]), "=r"(r[2]), "=r"(r[3]) : "r"(addr));
}
__device__ __forceinline__ void mma_f16(float (&d)[4], const uint32_t (&a)[4], uint2 b) {
    asm volatile("mma.sync.aligned.m16n8k16.row.col.f32.f16.f16.f32 "
        "{%0,%1,%2,%3}, {%4,%5,%6,%7}, {%8,%9}, {%0,%1,%2,%3};"
        : "+f"(d[0]), "+f"(d[1]), "+f"(d[2]), "+f"(d[3])
        : "r"(a[0]), "r"(a[1]), "r"(a[2]), "r"(a[3]), "r"(b.x), "r"(b.y));
}
__device__ __forceinline__ void blockReduce2_128(float& s, float& s2, float* red) {
#pragma unroll
    for (int off = 16; off > 0; off >>= 1) {
        s  += __shfl_xor_sync(0xffffffffu, s,  off);
        s2 += __shfl_xor_sync(0xffffffffu, s2, off);
    }
    int w = threadIdx.x >> 5;
    if ((threadIdx.x & 31) == 0) { red[w] = s; red[4 + w] = s2; }
    __syncthreads();
    s  = red[0] + red[1] + red[2] + red[3];
    s2 = red[4] + red[5] + red[6] + red[7];
    __syncthreads();
}

// ---------------- kernel: map_pos_embed MLP + projection (+ row stats, R10-verified) ----------------
__global__ __launch_bounds__(128) void k_mp(
    const float* __restrict__ mpl,
    const float* __restrict__ w0, const float* __restrict__ b0,
    const float* __restrict__ g0, const float* __restrict__ t0,
    const float* __restrict__ w1, const float* __restrict__ b1,
    const float* __restrict__ W0mla)
{
    __shared__ float xs[256], hs[128], mp[128], red[8];
    int m = blockIdx.x, j = threadIdx.x;
    xs[j] = mpl[m * 256 + j];
    xs[128 + j] = mpl[m * 256 + 128 + j];
    __syncthreads();

    float z = b0[j];
#pragma unroll 8
    for (int i = 0; i < 256; i++) z = fmaf(xs[i], w0[i * 128 + j], z);
    float s = z, s2 = z * z;
    blockReduce2_128(s, s2, red);
    float mean = s * (1.f / 128.f);
    float var = s2 * (1.f / 128.f) - mean * mean;
    float rs = rsqrtf(var + LN_EPS);
    hs[j] = fmaxf((z - mean) * rs * g0[j] + t0[j], 0.f);
    __syncthreads();

    float z1 = b1[j];
#pragma unroll 8
    for (int i = 0; i < 128; i++) z1 = fmaf(hs[i], w1[i * 128 + j], z1);
    mp[j] = z1;
    __syncthreads();

    float sl = 0.f, ql = 0.f;
#pragma unroll
    for (int q = 0; q < 4; q++) {
        int c = j + q * 128;
        float acc = 0.f;
#pragma unroll 8
        for (int i = 0; i < 128; i++) acc = fmaf(mp[i], W0mla[i * 512 + c], acc);
        g_MP0[m * 512 + c] = acc;
        sl += acc; ql += acc * acc;
    }
    blockReduce2_128(sl, ql, red);
    if (j == 0) { g_smp[m] = sl; g_qmp[m] = ql; }
}

// ---------------- kernel: codebook @ mla_w0 (+ row stats, R10-verified) ----------------
__global__ __launch_bounds__(128) void k_cb(
    const float* __restrict__ tok, const float* __restrict__ W0mla)
{
    __shared__ float cb[128], red[8];
    int lat = blockIdx.x, j = threadIdx.x;
    cb[j] = tok[lat * 128 + j];
    __syncthreads();
    float sl = 0.f, ql = 0.f;
#pragma unroll
    for (int q = 0; q < 4; q++) {
        int c = j + q * 128;
        float acc = 0.f;
#pragma unroll 8
        for (int i = 0; i < 128; i++) acc = fmaf(cb[i], W0mla[i * 512 + c], acc);
        g_CB0[lat * 512 + c] = acc;
        sl += acc; ql += acc * acc;
    }
    blockReduce2_128(sl, ql, red);
    if (j == 0) { g_scb[lat] = sl; g_qcb[lat] = ql; }
}

// ---------------- kernel: dot(CB0[lat], MP0[m]) (R10-verified) ----------------
__global__ __launch_bounds__(128) void k_dcm() {
    __shared__ float mp[512];
    int m = blockIdx.x, j = threadIdx.x;
#pragma unroll
    for (int i = 0; i < 4; i++) mp[j + i * 128] = g_MP0[m * 512 + j + i * 128];
    __syncthreads();
    const float4* c4 = (const float4*)(g_CB0 + j * 512);
    const float4* m4 = (const float4*)mp;
    float d = 0.f;
#pragma unroll 8
    for (int i = 0; i < 128; i++) {
        float4 a = c4[i], b = m4[i];
        d += a.x * b.x + a.y * b.y + a.z * b.z + a.w * b.w;
    }
    g_dcm[j * 64 + m] = d;
}

// ---------------- 4-wide LN+ReLU helper (R10-verified) ----------------
__device__ __forceinline__ void ln4(
    const float z[4], float gv, float tv, float (*dst)[128],
    float2 (*red)[4], int w, int l, int j)
{
    float s[4], q[4];
#pragma unroll
    for (int t = 0; t < 4; t++) { s[t] = z[t]; q[t] = z[t] * z[t]; }
#pragma unroll
    for (int off = 16; off > 0; off >>= 1) {
#pragma unroll
        for (int t = 0; t < 4; t++) {
            s[t] += __shfl_xor_sync(0xffffffffu, s[t], off);
            q[t] += __shfl_xor_sync(0xffffffffu, q[t], off);
        }
    }
    if (l == 0) {
#pragma unroll
        for (int t = 0; t < 4; t++) red[w][t] = make_float2(s[t], q[t]);
    }
    __syncthreads();
#pragma unroll
    for (int t = 0; t < 4; t++) {
        float ss = 0.f, qq = 0.f;
#pragma unroll
        for (int ww = 0; ww < 4; ww++) { float2 r = red[ww][t]; ss += r.x; qq += r.y; }
        float mean = ss * (1.f / 128.f);
        float var = qq * (1.f / 128.f) - mean * mean;
        float rs = rsqrtf(var + LN_EPS);
        dst[t][j] = fmaxf((z[t] - mean) * rs * gv + tv, 0.f);
    }
    __syncthreads();
}

// ---------------- kernel: agent_pos_emb MLP, 4 bt per block (+ stats, R10-verified) ----------------
__global__ __launch_bounds__(128) void k_ape4(
    const float* __restrict__ heading, const float* __restrict__ position,
    const float* __restrict__ w0, const float* __restrict__ b0,
    const float* __restrict__ g0, const float* __restrict__ t0,
    const float* __restrict__ w1, const float* __restrict__ b1,
    const float* __restrict__ g1, const float* __restrict__ t1,
    const float* __restrict__ w2, const float* __restrict__ b2,
    const float* __restrict__ W0mla, const float* __restrict__ b0mla)
{
    __shared__ float in_s[4][8];
    __shared__ float a_s[4][128];
    __shared__ float c_s[4][128];
    __shared__ float2 red_s[4][4];
    int j = threadIdx.x, w = j >> 5, l = j & 31;
    int bt0 = blockIdx.x * 4;

    if (j < 4) {
        int bt = bt0 + j, b = bt >> 7, t = bt & 127;
        float hd = heading[b * 4096 + t];
        float px = position[(b * 4096 + t) * 2 + 0];
        float py = position[(b * 4096 + t) * 2 + 1];
        in_s[j][0] = px; in_s[j][1] = py; in_s[j][2] = hd;
        in_s[j][3] = sinf(hd); in_s[j][4] = cosf(hd);
    }
    __syncthreads();

    float z[4];
    float bj = b0[j];
#pragma unroll
    for (int t = 0; t < 4; t++) z[t] = bj;
#pragma unroll
    for (int i = 0; i < 5; i++) {
        float wv = w0[i * 128 + j];
#pragma unroll
        for (int t = 0; t < 4; t++) z[t] = fmaf(in_s[t][i], wv, z[t]);
    }
    ln4(z, g0[j], t0[j], a_s, red_s, w, l, j);

    float bj1 = b1[j];
#pragma unroll
    for (int t = 0; t < 4; t++) z[t] = bj1;
#pragma unroll 4
    for (int i = 0; i < 128; i++) {
        float wv = w1[i * 128 + j];
#pragma unroll
        for (int t = 0; t < 4; t++) z[t] = fmaf(a_s[t][i], wv, z[t]);
    }
    ln4(z, g1[j], t1[j], c_s, red_s, w, l, j);

    float bj2 = b2[j];
#pragma unroll
    for (int t = 0; t < 4; t++) z[t] = bj2;
#pragma unroll 4
    for (int i = 0; i < 128; i++) {
        float wv = w2[i * 128 + j];
#pragma unroll
        for (int t = 0; t < 4; t++) z[t] = fmaf(c_s[t][i], wv, z[t]);
    }
    __syncthreads();
#pragma unroll
    for (int t = 0; t < 4; t++) a_s[t][j] = z[t];
    __syncthreads();

    float s_loc[4] = {0.f, 0.f, 0.f, 0.f};
    float q_loc[4] = {0.f, 0.f, 0.f, 0.f};
#pragma unroll
    for (int qd = 0; qd < 4; qd++) {
        int c = j + qd * 128;
        float acc[4];
        float bc = b0mla[c];
#pragma unroll
        for (int t = 0; t < 4; t++) acc[t] = bc;
#pragma unroll 4
        for (int i = 0; i < 128; i++) {
            float wv = W0mla[i * 512 + c];
#pragma unroll
            for (int t = 0; t < 4; t++) acc[t] = fmaf(a_s[t][i], wv, acc[t]);
        }
#pragma unroll
        for (int t = 0; t < 4; t++) {
            g_AP0[(bt0 + t) * 512 + c] = acc[t];
            s_loc[t] += acc[t];
            q_loc[t] += acc[t] * acc[t];
        }
    }
#pragma unroll
    for (int off = 16; off > 0; off >>= 1) {
#pragma unroll
        for (int t = 0; t < 4; t++) {
            s_loc[t] += __shfl_xor_sync(0xffffffffu, s_loc[t], off);
            q_loc[t] += __shfl_xor_sync(0xffffffffu, q_loc[t], off);
        }
    }
    if (l == 0) {
#pragma unroll
        for (int t = 0; t < 4; t++) red_s[w][t] = make_float2(s_loc[t], q_loc[t]);
    }
    __syncthreads();
    if (j < 4) {
        float ss = 0.f, qq = 0.f;
#pragma unroll
        for (int ww = 0; ww < 4; ww++) { float2 r = red_s[ww][j]; ss += r.x; qq += r.y; }
        g_sap[bt0 + j] = ss;
        g_qap[bt0 + j] = qq;
    }
}

// ---------------- kernel: TILED cross-dot GEMM  AP0 @ [CB0|MP0]^T ----------------
// grid (128, 3): bm = 64-bt tile, bn = 64-col tile (bn 0,1 -> CB0; bn 2 -> MP0)
#define DK_PAD 68
__global__ __launch_bounds__(256) void k_dots() {
    __shared__ float As[64][DK_PAD];
    __shared__ float Vs[64][DK_PAD];
    int tid = threadIdx.x;
    int tx = tid & 15, ty = tid >> 4;
    int bt0 = blockIdx.x * 64;
    int bn = blockIdx.y;
    const float* Vbase = (bn < 2) ? (g_CB0 + bn * 64 * 512) : g_MP0;

    float acc[4][4];
#pragma unroll
    for (int i = 0; i < 4; i++)
#pragma unroll
        for (int jj = 0; jj < 4; jj++) acc[i][jj] = 0.f;

    for (int kc = 0; kc < 8; kc++) {
#pragma unroll
        for (int it = 0; it < 4; it++) {
            int flat = it * 256 + tid;
            int r = flat >> 4, kq = flat & 15;
            float4 v = *(const float4*)(g_AP0 + (long)(bt0 + r) * 512 + kc * 64 + kq * 4);
            As[kq * 4 + 0][r] = v.x; As[kq * 4 + 1][r] = v.y;
            As[kq * 4 + 2][r] = v.z; As[kq * 4 + 3][r] = v.w;
        }
#pragma unroll
        for (int it = 0; it < 4; it++) {
            int flat = it * 256 + tid;
            int r = flat >> 4, kq = flat & 15;
            float4 v = *(const float4*)(Vbase + r * 512 + kc * 64 + kq * 4);
            Vs[kq * 4 + 0][r] = v.x; Vs[kq * 4 + 1][r] = v.y;
            Vs[kq * 4 + 2][r] = v.z; Vs[kq * 4 + 3][r] = v.w;
        }
        __syncthreads();
#pragma unroll 16
        for (int k = 0; k < 64; k++) {
            float4 a = *(const float4*)(&As[k][ty * 4]);
            float4 b = *(const float4*)(&Vs[k][tx * 4]);
            acc[0][0] = fmaf(a.x, b.x, acc[0][0]); acc[0][1] = fmaf(a.x, b.y, acc[0][1]);
            acc[0][2] = fmaf(a.x, b.z, acc[0][2]); acc[0][3] = fmaf(a.x, b.w, acc[0][3]);
            acc[1][0] = fmaf(a.y, b.x, acc[1][0]); acc[1][1] = fmaf(a.y, b.y, acc[1][1]);
            acc[1][2] = fmaf(a.y, b.z, acc[1][2]); acc[1][3] = fmaf(a.y, b.w, acc[1][3]);
            acc[2][0] = fmaf(a.z, b.x, acc[2][0]); acc[2][1] = fmaf(a.z, b.y, acc[2][1]);
            acc[2][2] = fmaf(a.z, b.z, acc[2][2]); acc[2][3] = fmaf(a.z, b.w, acc[2][3]);
            acc[3][0] = fmaf(a.w, b.x, acc[3][0]); acc[3][1] = fmaf(a.w, b.y, acc[3][1]);
            acc[3][2] = fmaf(a.w, b.z, acc[3][2]); acc[3][3] = fmaf(a.w, b.w, acc[3][3]);
        }
        __syncthreads();
    }

#pragma unroll
    for (int i = 0; i < 4; i++) {
        long bt = bt0 + ty * 4 + i;
#pragma unroll
        for (int jj = 0; jj < 4; jj++) {
            int c = bn * 64 + tx * 4 + jj;
            if (c < 128) g_dapcb[bt * 128 + c] = acc[i][jj];
            else         g_dapmp[bt * 64 + (c - 128)] = acc[i][jj];
        }
    }
}

// ---------------- kernel: pack W1 into mma-fragment order, fp16 ----------------
__global__ __launch_bounds__(256) void k_wt(const float* __restrict__ W1) {
    int idx = blockIdx.x * 256 + threadIdx.x;
    int r    = idx & 1;
    int lane = (idx >> 1) & 31;
    int nf   = (idx >> 6) & 15;
    int s    = (idx >> 10) & 7;
    int c    = (idx >> 13) & 3;
    int k_loc = s * 16 + (lane & 3) * 2 + r * 8;
    int col   = nf * 8 + (lane >> 2);
    int kg    = c * 128 + k_loc;
    float v0 = W1[kg * 128 + col];
    float v1 = W1[(kg + 1) * 128 + col];
    __half2 hp = __floats2half2_rn(v0, v1);
    g_Wf[(((c * 8 + s) * 16 + nf) * 32 + lane) * 2 + r] = *(uint32_t*)&hp;
}

// ---------------- main kernel: coalesced gather + table-stats LN + HMMA fp16 2-pass ----------------
#define SOFF_HHI  0
#define SOFF_HLO  32768
#define SOFF_B    65536
#define SOFF_AP   98304
#define SOFF_GS   102400
#define SOFF_TS   104448
#define SOFF_LAT  106496
#define SOFF_MEAN 107008
#define SOFF_RS   107520
#define SOFF_B1   108032
#define SMEM_BYTES 108544

__global__ __launch_bounds__(256, 2) void k_main(
    const int* __restrict__ lat_idx,
    const float* __restrict__ b1,
    const float* __restrict__ g0, const float* __restrict__ t0,
    float* __restrict__ out)
{
    extern __shared__ char smem[];
    float* ap_s   = (float*)(smem + SOFF_AP);
    float* gs_s   = (float*)(smem + SOFF_GS);
    float* ts_s   = (float*)(smem + SOFF_TS);
    int*   lat_s  = (int*)(smem + SOFF_LAT);
    float* mean_s = (float*)(smem + SOFF_MEAN);
    float* rs_s   = (float*)(smem + SOFF_RS);
    float* b1_s   = (float*)(smem + SOFF_B1);
    uint2* B2     = (uint2*)(smem + SOFF_B);

    int tid = threadIdx.x, wid = tid >> 5, lane = tid & 31;
    int p = blockIdx.x;

    for (int i = tid; i < 1024; i += 256) ap_s[i] = g_AP0[p * 1024 + i];
    for (int i = tid; i < 512; i += 256) { gs_s[i] = g0[i]; ts_s[i] = t0[i]; }
    if (tid < 128) {
        int lat = lat_idx[p * 128 + tid];
        lat_s[tid] = lat;
        b1_s[tid] = b1[tid];
        // LN stats from precomputed tables (R10-verified numerics)
        int m = tid & 63;
        int btg = p * 2 + (tid >> 6);
        float sum = g_scb[lat] + g_smp[m] + g_sap[btg];
        float ssq = g_qcb[lat] + g_qmp[m] + g_qap[btg]
                  + 2.f * (g_dcm[lat * 64 + m] + g_dapcb[(long)btg * 128 + lat] + g_dapmp[(long)btg * 64 + m]);
        float mean = sum * (1.f / 512.f);
        float var = ssq * (1.f / 512.f) - mean * mean;
        mean_s[tid] = mean;
        rs_s[tid] = rsqrtf(var + LN_EPS);
    }
    __syncthreads();

    // warp tiling for mma: 4 row-groups x 2 col-groups
    int rg = wid >> 1, cg = wid & 1;
    int R = rg * 32;
    int mat = lane >> 3, rl = lane & 7;
    int rowA0 = R + ((mat & 1) << 3) + rl;
    uint32_t sbH = smem_u32(smem) + SOFF_HHI;
    uint32_t sbL = smem_u32(smem) + SOFF_HLO;

    float acc0[8][4], acc1[8][4];
#pragma unroll
    for (int nf = 0; nf < 8; nf++)
#pragma unroll
        for (int i = 0; i < 4; i++) { acc0[nf][i] = 0.f; acc1[nf][i] = 0.f; }

    int uB = lane >> 1;
    uint32_t stsOff = (uint32_t)((lane & 1) * 8);

    for (int c = 0; c < 4; c++) {
        // ---- copy W frag chunk (32KB) ----
        {
            const uint4* src = (const uint4*)(g_Wf + c * 8192);
            uint4* dst = (uint4*)(smem + SOFF_B);
#pragma unroll
            for (int i = 0; i < 8; i++) dst[i * 256 + tid] = src[i * 256 + tid];
        }
        // ---- build H chunk: warp-per-row, lanes span k (coalesced) ----
        {
            int kg = c * 128 + lane * 4;
#pragma unroll 2
            for (int rr = 0; rr < 16; rr++) {
                int r = wid * 16 + rr;
                float4 a = *(const float4*)(g_CB0 + lat_s[r] * 512 + kg);
                float4 b = *(const float4*)(g_MP0 + (r & 63) * 512 + kg);
                float4 e = *(const float4*)(ap_s + (r >> 6) * 512 + kg);
                float4 gv = *(const float4*)(gs_s + kg);
                float4 tv = *(const float4*)(ts_s + kg);
                float mean = mean_s[r], rsv = rs_s[r];
                float h0 = fmaxf(fmaf((a.x + b.x + e.x - mean) * rsv, gv.x, tv.x), 0.f);
                float h1 = fmaxf(fmaf((a.y + b.y + e.y - mean) * rsv, gv.y, tv.y), 0.f);
                float h2 = fmaxf(fmaf((a.z + b.z + e.z - mean) * rsv, gv.z, tv.z), 0.f);
                float h3 = fmaxf(fmaf((a.w + b.w + e.w - mean) * rsv, gv.w, tv.w), 0.f);
                __half q0 = __float2half_rn(h0), q1 = __float2half_rn(h1);
                __half q2 = __float2half_rn(h2), q3 = __float2half_rn(h3);
                __half2 hp0 = __halves2half2(q0, q1);
                __half2 hp1 = __halves2half2(q2, q3);
                __half2 lp0 = __floats2half2_rn(h0 - __half2float(q0), h1 - __half2float(q1));
                __half2 lp1 = __floats2half2_rn(h2 - __half2float(q2), h3 - __half2float(q3));
                uint32_t sw = (uint32_t)r * 256 + (uint32_t)((uB ^ (r & 7)) << 4) + stsOff;
                *(uint2*)(smem + SOFF_HHI + sw) = make_uint2(*(uint32_t*)&hp0, *(uint32_t*)&hp1);
                *(uint2*)(smem + SOFF_HLO + sw) = make_uint2(*(uint32_t*)&lp0, *(uint32_t*)&lp1);
            }
        }
        __syncthreads();

        // ---- mma: 2-pass (H = hi + lo), single W plane ----
#pragma unroll
        for (int s = 0; s < 8; s++) {
            uint32_t ah0[4], ah1[4], al0[4], al1[4];
            int u0 = s * 2 + (mat >> 1);
            int r0 = rowA0, r1 = rowA0 + 16;
            uint32_t off0 = (uint32_t)r0 * 256 + (uint32_t)((u0 ^ (r0 & 7)) << 4);
            uint32_t off1 = (uint32_t)r1 * 256 + (uint32_t)((u0 ^ (r1 & 7)) << 4);
            ldsm4(ah0, sbH + off0);
            ldsm4(ah1, sbH + off1);
            ldsm4(al0, sbL + off0);
            ldsm4(al1, sbL + off1);
#pragma unroll
            for (int nf = 0; nf < 8; nf++) {
                int nfg = cg * 8 + nf;
                uint2 bw = B2[(s * 16 + nfg) * 32 + lane];
                mma_f16(acc0[nf], ah0, bw);
                mma_f16(acc1[nf], ah1, bw);
                mma_f16(acc0[nf], al0, bw);
                mma_f16(acc1[nf], al1, bw);
            }
        }
        __syncthreads();
    }

    // ---- epilogue ----
    {
        int r0 = R + (lane >> 2);
        int colb = cg * 64 + (lane & 3) * 2;
        long rowg = (long)p * 128;
#pragma unroll
        for (int nf = 0; nf < 8; nf++) {
            int col = colb + nf * 8;
            float ba = b1_s[col], bb = b1_s[col + 1];
            float* o0 = out + (rowg + r0) * 128 + col;
            *(float2*)o0 = make_float2(acc0[nf][0] + ba, acc0[nf][1] + bb);
            *(float2*)(o0 + 8 * 128) = make_float2(acc0[nf][2] + ba, acc0[nf][3] + bb);
            float* o1 = out + (rowg + r0 + 16) * 128 + col;
            *(float2*)o1 = make_float2(acc1[nf][0] + ba, acc1[nf][1] + bb);
            *(float2*)(o1 + 8 * 128) = make_float2(acc1[nf][2] + ba, acc1[nf][3] + bb);
        }
    }
}

// ---------------- launch ----------------
extern "C" void kernel_launch(void* const* d_in, const int* in_sizes, int n_in,
                              void* d_out, int out_size) {
    const int*   map_latent = (const int*)d_in[0];
    const float* heading    = (const float*)d_in[1];
    const float* position   = (const float*)d_in[2];
    const float* tokenizer  = (const float*)d_in[3];
    const float* mpl        = (const float*)d_in[4];
    const float* ape_w0 = (const float*)d_in[5];
    const float* ape_b0 = (const float*)d_in[6];
    const float* ape_g0 = (const float*)d_in[7];
    const float* ape_t0 = (const float*)d_in[8];
    const float* ape_w1 = (const float*)d_in[9];
    const float* ape_b1 = (const float*)d_in[10];
    const float* ape_g1 = (const float*)d_in[11];
    const float* ape_t1 = (const float*)d_in[12];
    const float* ape_w2 = (const float*)d_in[13];
    const float* ape_b2 = (const float*)d_in[14];
    const float* mla_w0 = (const float*)d_in[15];
    const float* mla_b0 = (const float*)d_in[16];
    const float* mla_g0 = (const float*)d_in[17];
    const float* mla_t0 = (const float*)d_in[18];
    const float* mla_w1 = (const float*)d_in[19];
    const float* mla_b1 = (const float*)d_in[20];
    const float* mpm_w0 = (const float*)d_in[21];
    const float* mpm_b0 = (const float*)d_in[22];
    const float* mpm_g0 = (const float*)d_in[23];
    const float* mpm_t0 = (const float*)d_in[24];
    const float* mpm_w1 = (const float*)d_in[25];
    const float* mpm_b1 = (const float*)d_in[26];
    float* out = (float*)d_out;

    cudaFuncSetAttribute(k_main, cudaFuncAttributeMaxDynamicSharedMemorySize, SMEM_BYTES);

    k_mp<<<64, 128>>>(mpl, mpm_w0, mpm_b0, mpm_g0, mpm_t0, mpm_w1, mpm_b1, mla_w0);
    k_cb<<<128, 128>>>(tokenizer, mla_w0);
    k_dcm<<<64, 128>>>();
    k_wt<<<128, 256>>>(mla_w1);
    k_ape4<<<2048, 128>>>(heading, position,
                          ape_w0, ape_b0, ape_g0, ape_t0,
                          ape_w1, ape_b1, ape_g1, ape_t1,
                          ape_w2, ape_b2, mla_w0, mla_b0);
    {
        dim3 gdots(128, 3);
        k_dots<<<gdots, 256>>>();
    }
    k_main<<<4096, 256, SMEM_BYTES>>>(map_latent, mla_b1, mla_g0, mla_t0, out);
}

// round 17
// speedup vs baseline: 2.6198x; 1.1897x over previous
#include <cuda_runtime.h>
#include <cuda_fp16.h>
#include <cstdint>
#include <math.h>

#define LN_EPS 1e-5f

// ---------------- device scratch ----------------
__device__ float g_CB0[128 * 512];
__device__ float g_MP0[64 * 512];
__device__ float g_AP0[8192 * 512];
__device__ uint32_t g_Wf[32768];          // W1 frag-packed fp16
__device__ float g_scb[128], g_qcb[128];
__device__ float g_smp[64],  g_qmp[64];
__device__ float g_sap[8192], g_qap[8192];
__device__ float g_dapcb[8192 * 128];
__device__ float g_dapmp[8192 * 64];
__device__ float g_dcm[128 * 64];

// ---------------- helpers ----------------
__device__ __forceinline__ uint32_t smem_u32(const void* p) {
    uint32_t a;
    asm("{ .reg .u64 t; cvta.to.shared.u64 t, %1; cvt.u32.u64 %0, t; }" : "=r"(a) : "l"(p));
    return a;
}
__device__ __forceinline__ void ldsm4(uint32_t (&r)[4], uint32_t addr) {
    asm volatile("ldmatrix.sync.aligned.m8n8.x4.shared.b16 {%0,%1,%2,%3}, [%4];"
        : "=r"(r[0]), "=r"(r[1]), "=r"(r[2]), "=r"(r[3]) : "r"(addr));
}
__device__ __forceinline__ void mma_f16(float (&d)[4], const uint32_t (&a)[4], uint2 b) {
    asm volatile("mma.sync.aligned.m16n8k16.row.col.f32.f16.f16.f32 "
        "{%0,%1,%2,%3}, {%4,%5,%6,%7}, {%8,%9}, {%0,%1,%2,%3};"
        : "+f"(d[0]), "+f"(d[1]), "+f"(d[2]), "+f"(d[3])
        : "r"(a[0]), "r"(a[1]), "r"(a[2]), "r"(a[3]), "r"(b.x), "r"(b.y));
}
__device__ __forceinline__ void blockReduce2_128(float& s, float& s2, float* red) {
#pragma unroll
    for (int off = 16; off > 0; off >>= 1) {
        s  += __shfl_xor_sync(0xffffffffu, s,  off);
        s2 += __shfl_xor_sync(0xffffffffu, s2, off);
    }
    int w = threadIdx.x >> 5;
    if ((threadIdx.x & 31) == 0) { red[w] = s; red[4 + w] = s2; }
    __syncthreads();
    s  = red[0] + red[1] + red[2] + red[3];
    s2 = red[4] + red[5] + red[6] + red[7];
    __syncthreads();
}

// ---------------- kernel: map_pos_embed MLP + projection (+ row stats) ----------------
__global__ __launch_bounds__(128) void k_mp(
    const float* __restrict__ mpl,
    const float* __restrict__ w0, const float* __restrict__ b0,
    const float* __restrict__ g0, const float* __restrict__ t0,
    const float* __restrict__ w1, const float* __restrict__ b1,
    const float* __restrict__ W0mla)
{
    __shared__ float xs[256], hs[128], mp[128], red[8];
    int m = blockIdx.x, j = threadIdx.x;
    xs[j] = mpl[m * 256 + j];
    xs[128 + j] = mpl[m * 256 + 128 + j];
    __syncthreads();

    float z = b0[j];
#pragma unroll 8
    for (int i = 0; i < 256; i++) z = fmaf(xs[i], w0[i * 128 + j], z);
    float s = z, s2 = z * z;
    blockReduce2_128(s, s2, red);
    float mean = s * (1.f / 128.f);
    float var = s2 * (1.f / 128.f) - mean * mean;
    float rs = rsqrtf(var + LN_EPS);
    hs[j] = fmaxf((z - mean) * rs * g0[j] + t0[j], 0.f);
    __syncthreads();

    float z1 = b1[j];
#pragma unroll 8
    for (int i = 0; i < 128; i++) z1 = fmaf(hs[i], w1[i * 128 + j], z1);
    mp[j] = z1;
    __syncthreads();

    float sl = 0.f, ql = 0.f;
#pragma unroll
    for (int q = 0; q < 4; q++) {
        int c = j + q * 128;
        float acc = 0.f;
#pragma unroll 8
        for (int i = 0; i < 128; i++) acc = fmaf(mp[i], W0mla[i * 512 + c], acc);
        g_MP0[m * 512 + c] = acc;
        sl += acc; ql += acc * acc;
    }
    blockReduce2_128(sl, ql, red);
    if (j == 0) { g_smp[m] = sl; g_qmp[m] = ql; }
}

// ---------------- kernel: codebook @ mla_w0 (+ row stats) ----------------
__global__ __launch_bounds__(128) void k_cb(
    const float* __restrict__ tok, const float* __restrict__ W0mla)
{
    __shared__ float cb[128], red[8];
    int lat = blockIdx.x, j = threadIdx.x;
    cb[j] = tok[lat * 128 + j];
    __syncthreads();
    float sl = 0.f, ql = 0.f;
#pragma unroll
    for (int q = 0; q < 4; q++) {
        int c = j + q * 128;
        float acc = 0.f;
#pragma unroll 8
        for (int i = 0; i < 128; i++) acc = fmaf(cb[i], W0mla[i * 512 + c], acc);
        g_CB0[lat * 512 + c] = acc;
        sl += acc; ql += acc * acc;
    }
    blockReduce2_128(sl, ql, red);
    if (j == 0) { g_scb[lat] = sl; g_qcb[lat] = ql; }
}

// ---------------- kernel: dot(CB0[lat], MP0[m]) ----------------
__global__ __launch_bounds__(128) void k_dcm() {
    __shared__ float mp[512];
    int m = blockIdx.x, j = threadIdx.x;
#pragma unroll
    for (int i = 0; i < 4; i++) mp[j + i * 128] = g_MP0[m * 512 + j + i * 128];
    __syncthreads();
    const float4* c4 = (const float4*)(g_CB0 + j * 512);
    const float4* m4 = (const float4*)mp;
    float d = 0.f;
#pragma unroll 8
    for (int i = 0; i < 128; i++) {
        float4 a = c4[i], b = m4[i];
        d += a.x * b.x + a.y * b.y + a.z * b.z + a.w * b.w;
    }
    g_dcm[j * 64 + m] = d;
}

// ---------------- 4-wide LN+ReLU helper ----------------
__device__ __forceinline__ void ln4(
    const float z[4], float gv, float tv, float (*dst)[128],
    float2 (*red)[4], int w, int l, int j)
{
    float s[4], q[4];
#pragma unroll
    for (int t = 0; t < 4; t++) { s[t] = z[t]; q[t] = z[t] * z[t]; }
#pragma unroll
    for (int off = 16; off > 0; off >>= 1) {
#pragma unroll
        for (int t = 0; t < 4; t++) {
            s[t] += __shfl_xor_sync(0xffffffffu, s[t], off);
            q[t] += __shfl_xor_sync(0xffffffffu, q[t], off);
        }
    }
    if (l == 0) {
#pragma unroll
        for (int t = 0; t < 4; t++) red[w][t] = make_float2(s[t], q[t]);
    }
    __syncthreads();
#pragma unroll
    for (int t = 0; t < 4; t++) {
        float ss = 0.f, qq = 0.f;
#pragma unroll
        for (int ww = 0; ww < 4; ww++) { float2 r = red[ww][t]; ss += r.x; qq += r.y; }
        float mean = ss * (1.f / 128.f);
        float var = qq * (1.f / 128.f) - mean * mean;
        float rs = rsqrtf(var + LN_EPS);
        dst[t][j] = fmaxf((z[t] - mean) * rs * gv + tv, 0.f);
    }
    __syncthreads();
}

// ---------------- kernel: agent_pos_emb MLP, 4 bt per block (+ stats) ----------------
__global__ __launch_bounds__(128) void k_ape4(
    const float* __restrict__ heading, const float* __restrict__ position,
    const float* __restrict__ w0, const float* __restrict__ b0,
    const float* __restrict__ g0, const float* __restrict__ t0,
    const float* __restrict__ w1, const float* __restrict__ b1,
    const float* __restrict__ g1, const float* __restrict__ t1,
    const float* __restrict__ w2, const float* __restrict__ b2,
    const float* __restrict__ W0mla, const float* __restrict__ b0mla)
{
    __shared__ float in_s[4][8];
    __shared__ float a_s[4][128];
    __shared__ float c_s[4][128];
    __shared__ float2 red_s[4][4];
    int j = threadIdx.x, w = j >> 5, l = j & 31;
    int bt0 = blockIdx.x * 4;

    if (j < 4) {
        int bt = bt0 + j, b = bt >> 7, t = bt & 127;
        float hd = heading[b * 4096 + t];
        float px = position[(b * 4096 + t) * 2 + 0];
        float py = position[(b * 4096 + t) * 2 + 1];
        in_s[j][0] = px; in_s[j][1] = py; in_s[j][2] = hd;
        in_s[j][3] = sinf(hd); in_s[j][4] = cosf(hd);
    }
    __syncthreads();

    float z[4];
    float bj = b0[j];
#pragma unroll
    for (int t = 0; t < 4; t++) z[t] = bj;
#pragma unroll
    for (int i = 0; i < 5; i++) {
        float wv = w0[i * 128 + j];
#pragma unroll
        for (int t = 0; t < 4; t++) z[t] = fmaf(in_s[t][i], wv, z[t]);
    }
    ln4(z, g0[j], t0[j], a_s, red_s, w, l, j);

    float bj1 = b1[j];
#pragma unroll
    for (int t = 0; t < 4; t++) z[t] = bj1;
#pragma unroll 4
    for (int i = 0; i < 128; i++) {
        float wv = w1[i * 128 + j];
#pragma unroll
        for (int t = 0; t < 4; t++) z[t] = fmaf(a_s[t][i], wv, z[t]);
    }
    ln4(z, g1[j], t1[j], c_s, red_s, w, l, j);

    float bj2 = b2[j];
#pragma unroll
    for (int t = 0; t < 4; t++) z[t] = bj2;
#pragma unroll 4
    for (int i = 0; i < 128; i++) {
        float wv = w2[i * 128 + j];
#pragma unroll
        for (int t = 0; t < 4; t++) z[t] = fmaf(c_s[t][i], wv, z[t]);
    }
    __syncthreads();
#pragma unroll
    for (int t = 0; t < 4; t++) a_s[t][j] = z[t];
    __syncthreads();

    float s_loc[4] = {0.f, 0.f, 0.f, 0.f};
    float q_loc[4] = {0.f, 0.f, 0.f, 0.f};
#pragma unroll
    for (int qd = 0; qd < 4; qd++) {
        int c = j + qd * 128;
        float acc[4];
        float bc = b0mla[c];
#pragma unroll
        for (int t = 0; t < 4; t++) acc[t] = bc;
#pragma unroll 4
        for (int i = 0; i < 128; i++) {
            float wv = W0mla[i * 512 + c];
#pragma unroll
            for (int t = 0; t < 4; t++) acc[t] = fmaf(a_s[t][i], wv, acc[t]);
        }
#pragma unroll
        for (int t = 0; t < 4; t++) {
            g_AP0[(bt0 + t) * 512 + c] = acc[t];
            s_loc[t] += acc[t];
            q_loc[t] += acc[t] * acc[t];
        }
    }
#pragma unroll
    for (int off = 16; off > 0; off >>= 1) {
#pragma unroll
        for (int t = 0; t < 4; t++) {
            s_loc[t] += __shfl_xor_sync(0xffffffffu, s_loc[t], off);
            q_loc[t] += __shfl_xor_sync(0xffffffffu, q_loc[t], off);
        }
    }
    if (l == 0) {
#pragma unroll
        for (int t = 0; t < 4; t++) red_s[w][t] = make_float2(s_loc[t], q_loc[t]);
    }
    __syncthreads();
    if (j < 4) {
        float ss = 0.f, qq = 0.f;
#pragma unroll
        for (int ww = 0; ww < 4; ww++) { float2 r = red_s[ww][j]; ss += r.x; qq += r.y; }
        g_sap[bt0 + j] = ss;
        g_qap[bt0 + j] = qq;
    }
}

// ---------------- kernel: TILED cross-dot GEMM  AP0 @ [CB0|MP0]^T ----------------
#define DK_PAD 68
__global__ __launch_bounds__(256) void k_dots() {
    __shared__ float As[64][DK_PAD];
    __shared__ float Vs[64][DK_PAD];
    int tid = threadIdx.x;
    int tx = tid & 15, ty = tid >> 4;
    int bt0 = blockIdx.x * 64;
    int bn = blockIdx.y;
    const float* Vbase = (bn < 2) ? (g_CB0 + bn * 64 * 512) : g_MP0;

    float acc[4][4];
#pragma unroll
    for (int i = 0; i < 4; i++)
#pragma unroll
        for (int jj = 0; jj < 4; jj++) acc[i][jj] = 0.f;

    for (int kc = 0; kc < 8; kc++) {
#pragma unroll
        for (int it = 0; it < 4; it++) {
            int flat = it * 256 + tid;
            int r = flat >> 4, kq = flat & 15;
            float4 v = *(const float4*)(g_AP0 + (long)(bt0 + r) * 512 + kc * 64 + kq * 4);
            As[kq * 4 + 0][r] = v.x; As[kq * 4 + 1][r] = v.y;
            As[kq * 4 + 2][r] = v.z; As[kq * 4 + 3][r] = v.w;
        }
#pragma unroll
        for (int it = 0; it < 4; it++) {
            int flat = it * 256 + tid;
            int r = flat >> 4, kq = flat & 15;
            float4 v = *(const float4*)(Vbase + r * 512 + kc * 64 + kq * 4);
            Vs[kq * 4 + 0][r] = v.x; Vs[kq * 4 + 1][r] = v.y;
            Vs[kq * 4 + 2][r] = v.z; Vs[kq * 4 + 3][r] = v.w;
        }
        __syncthreads();
#pragma unroll 16
        for (int k = 0; k < 64; k++) {
            float4 a = *(const float4*)(&As[k][ty * 4]);
            float4 b = *(const float4*)(&Vs[k][tx * 4]);
            acc[0][0] = fmaf(a.x, b.x, acc[0][0]); acc[0][1] = fmaf(a.x, b.y, acc[0][1]);
            acc[0][2] = fmaf(a.x, b.z, acc[0][2]); acc[0][3] = fmaf(a.x, b.w, acc[0][3]);
            acc[1][0] = fmaf(a.y, b.x, acc[1][0]); acc[1][1] = fmaf(a.y, b.y, acc[1][1]);
            acc[1][2] = fmaf(a.y, b.z, acc[1][2]); acc[1][3] = fmaf(a.y, b.w, acc[1][3]);
            acc[2][0] = fmaf(a.z, b.x, acc[2][0]); acc[2][1] = fmaf(a.z, b.y, acc[2][1]);
            acc[2][2] = fmaf(a.z, b.z, acc[2][2]); acc[2][3] = fmaf(a.z, b.w, acc[2][3]);
            acc[3][0] = fmaf(a.w, b.x, acc[3][0]); acc[3][1] = fmaf(a.w, b.y, acc[3][1]);
            acc[3][2] = fmaf(a.w, b.z, acc[3][2]); acc[3][3] = fmaf(a.w, b.w, acc[3][3]);
        }
        __syncthreads();
    }

#pragma unroll
    for (int i = 0; i < 4; i++) {
        long bt = bt0 + ty * 4 + i;
#pragma unroll
        for (int jj = 0; jj < 4; jj++) {
            int c = bn * 64 + tx * 4 + jj;
            if (c < 128) g_dapcb[bt * 128 + c] = acc[i][jj];
            else         g_dapmp[bt * 64 + (c - 128)] = acc[i][jj];
        }
    }
}

// ---------------- kernel: pack W1 into mma-fragment order, fp16 ----------------
__global__ __launch_bounds__(256) void k_wt(const float* __restrict__ W1) {
    int idx = blockIdx.x * 256 + threadIdx.x;
    int r    = idx & 1;
    int lane = (idx >> 1) & 31;
    int nf   = (idx >> 6) & 15;
    int s    = (idx >> 10) & 7;
    int c    = (idx >> 13) & 3;
    int k_loc = s * 16 + (lane & 3) * 2 + r * 8;
    int col   = nf * 8 + (lane >> 2);
    int kg    = c * 128 + k_loc;
    float v0 = W1[kg * 128 + col];
    float v1 = W1[(kg + 1) * 128 + col];
    __half2 hp = __floats2half2_rn(v0, v1);
    g_Wf[(((c * 8 + s) * 16 + nf) * 32 + lane) * 2 + r] = *(uint32_t*)&hp;
}

// ---------------- main kernel: coalesced gather + table-stats LN + HMMA fp16 SINGLE-pass ----------------
#define SOFF_HHI  0
#define SOFF_B    32768
#define SOFF_AP   65536
#define SOFF_GS   69632
#define SOFF_TS   71680
#define SOFF_LAT  73728
#define SOFF_MEAN 74240
#define SOFF_RS   74752
#define SOFF_B1   75264
#define SMEM_BYTES 75776

__global__ __launch_bounds__(256, 2) void k_main(
    const int* __restrict__ lat_idx,
    const float* __restrict__ b1,
    const float* __restrict__ g0, const float* __restrict__ t0,
    float* __restrict__ out)
{
    extern __shared__ char smem[];
    float* ap_s   = (float*)(smem + SOFF_AP);
    float* gs_s   = (float*)(smem + SOFF_GS);
    float* ts_s   = (float*)(smem + SOFF_TS);
    int*   lat_s  = (int*)(smem + SOFF_LAT);
    float* mean_s = (float*)(smem + SOFF_MEAN);
    float* rs_s   = (float*)(smem + SOFF_RS);
    float* b1_s   = (float*)(smem + SOFF_B1);
    uint2* B2     = (uint2*)(smem + SOFF_B);

    int tid = threadIdx.x, wid = tid >> 5, lane = tid & 31;
    int p = blockIdx.x;

    for (int i = tid; i < 1024; i += 256) ap_s[i] = g_AP0[p * 1024 + i];
    for (int i = tid; i < 512; i += 256) { gs_s[i] = g0[i]; ts_s[i] = t0[i]; }
    if (tid < 128) {
        int lat = lat_idx[p * 128 + tid];
        lat_s[tid] = lat;
        b1_s[tid] = b1[tid];
        int m = tid & 63;
        int btg = p * 2 + (tid >> 6);
        float sum = g_scb[lat] + g_smp[m] + g_sap[btg];
        float ssq = g_qcb[lat] + g_qmp[m] + g_qap[btg]
                  + 2.f * (g_dcm[lat * 64 + m] + g_dapcb[(long)btg * 128 + lat] + g_dapmp[(long)btg * 64 + m]);
        float mean = sum * (1.f / 512.f);
        float var = ssq * (1.f / 512.f) - mean * mean;
        mean_s[tid] = mean;
        rs_s[tid] = rsqrtf(var + LN_EPS);
    }
    __syncthreads();

    // warp tiling for mma: 4 row-groups x 2 col-groups
    int rg = wid >> 1, cg = wid & 1;
    int R = rg * 32;
    int mat = lane >> 3, rl = lane & 7;
    int rowA0 = R + ((mat & 1) << 3) + rl;
    uint32_t sbH = smem_u32(smem) + SOFF_HHI;

    float acc0[8][4], acc1[8][4];
#pragma unroll
    for (int nf = 0; nf < 8; nf++)
#pragma unroll
        for (int i = 0; i < 4; i++) { acc0[nf][i] = 0.f; acc1[nf][i] = 0.f; }

    int uB = lane >> 1;
    uint32_t stsOff = (uint32_t)((lane & 1) * 8);

    for (int c = 0; c < 4; c++) {
        // ---- copy W frag chunk (32KB) ----
        {
            const uint4* src = (const uint4*)(g_Wf + c * 8192);
            uint4* dst = (uint4*)(smem + SOFF_B);
#pragma unroll
            for (int i = 0; i < 8; i++) dst[i * 256 + tid] = src[i * 256 + tid];
        }
        // ---- build H chunk: warp-per-row, lanes span k (coalesced), single fp16 plane ----
        {
            int kg = c * 128 + lane * 4;
#pragma unroll 2
            for (int rr = 0; rr < 16; rr++) {
                int r = wid * 16 + rr;
                float4 a = *(const float4*)(g_CB0 + lat_s[r] * 512 + kg);
                float4 b = *(const float4*)(g_MP0 + (r & 63) * 512 + kg);
                float4 e = *(const float4*)(ap_s + (r >> 6) * 512 + kg);
                float4 gv = *(const float4*)(gs_s + kg);
                float4 tv = *(const float4*)(ts_s + kg);
                float mean = mean_s[r], rsv = rs_s[r];
                float h0 = fmaxf(fmaf((a.x + b.x + e.x - mean) * rsv, gv.x, tv.x), 0.f);
                float h1 = fmaxf(fmaf((a.y + b.y + e.y - mean) * rsv, gv.y, tv.y), 0.f);
                float h2 = fmaxf(fmaf((a.z + b.z + e.z - mean) * rsv, gv.z, tv.z), 0.f);
                float h3 = fmaxf(fmaf((a.w + b.w + e.w - mean) * rsv, gv.w, tv.w), 0.f);
                __half2 hp0 = __floats2half2_rn(h0, h1);
                __half2 hp1 = __floats2half2_rn(h2, h3);
                uint32_t sw = (uint32_t)r * 256 + (uint32_t)((uB ^ (r & 7)) << 4) + stsOff;
                *(uint2*)(smem + SOFF_HHI + sw) = make_uint2(*(uint32_t*)&hp0, *(uint32_t*)&hp1);
            }
        }
        __syncthreads();

        // ---- mma: single pass ----
#pragma unroll
        for (int s = 0; s < 8; s++) {
            uint32_t ah0[4], ah1[4];
            int u0 = s * 2 + (mat >> 1);
            int r0 = rowA0, r1 = rowA0 + 16;
            uint32_t off0 = (uint32_t)r0 * 256 + (uint32_t)((u0 ^ (r0 & 7)) << 4);
            uint32_t off1 = (uint32_t)r1 * 256 + (uint32_t)((u0 ^ (r1 & 7)) << 4);
            ldsm4(ah0, sbH + off0);
            ldsm4(ah1, sbH + off1);
#pragma unroll
            for (int nf = 0; nf < 8; nf++) {
                int nfg = cg * 8 + nf;
                uint2 bw = B2[(s * 16 + nfg) * 32 + lane];
                mma_f16(acc0[nf], ah0, bw);
                mma_f16(acc1[nf], ah1, bw);
            }
        }
        __syncthreads();
    }

    // ---- epilogue ----
    {
        int r0 = R + (lane >> 2);
        int colb = cg * 64 + (lane & 3) * 2;
        long rowg = (long)p * 128;
#pragma unroll
        for (int nf = 0; nf < 8; nf++) {
            int col = colb + nf * 8;
            float ba = b1_s[col], bb = b1_s[col + 1];
            float* o0 = out + (rowg + r0) * 128 + col;
            *(float2*)o0 = make_float2(acc0[nf][0] + ba, acc0[nf][1] + bb);
            *(float2*)(o0 + 8 * 128) = make_float2(acc0[nf][2] + ba, acc0[nf][3] + bb);
            float* o1 = out + (rowg + r0 + 16) * 128 + col;
            *(float2*)o1 = make_float2(acc1[nf][0] + ba, acc1[nf][1] + bb);
            *(float2*)(o1 + 8 * 128) = make_float2(acc1[nf][2] + ba, acc1[nf][3] + bb);
        }
    }
}

// ---------------- launch ----------------
extern "C" void kernel_launch(void* const* d_in, const int* in_sizes, int n_in,
                              void* d_out, int out_size) {
    const int*   map_latent = (const int*)d_in[0];
    const float* heading    = (const float*)d_in[1];
    const float* position   = (const float*)d_in[2];
    const float* tokenizer  = (const float*)d_in[3];
    const float* mpl        = (const float*)d_in[4];
    const float* ape_w0 = (const float*)d_in[5];
    const float* ape_b0 = (const float*)d_in[6];
    const float* ape_g0 = (const float*)d_in[7];
    const float* ape_t0 = (const float*)d_in[8];
    const float* ape_w1 = (const float*)d_in[9];
    const float* ape_b1 = (const float*)d_in[10];
    const float* ape_g1 = (const float*)d_in[11];
    const float* ape_t1 = (const float*)d_in[12];
    const float* ape_w2 = (const float*)d_in[13];
    const float* ape_b2 = (const float*)d_in[14];
    const float* mla_w0 = (const float*)d_in[15];
    const float* mla_b0 = (const float*)d_in[16];
    const float* mla_g0 = (const float*)d_in[17];
    const float* mla_t0 = (const float*)d_in[18];
    const float* mla_w1 = (const float*)d_in[19];
    const float* mla_b1 = (const float*)d_in[20];
    const float* mpm_w0 = (const float*)d_in[21];
    const float* mpm_b0 = (const float*)d_in[22];
    const float* mpm_g0 = (const float*)d_in[23];
    const float* mpm_t0 = (const float*)d_in[24];
    const float* mpm_w1 = (const float*)d_in[25];
    const float* mpm_b1 = (const float*)d_in[26];
    float* out = (float*)d_out;

    cudaFuncSetAttribute(k_main, cudaFuncAttributeMaxDynamicSharedMemorySize, SMEM_BYTES);

    k_mp<<<64, 128>>>(mpl, mpm_w0, mpm_b0, mpm_g0, mpm_t0, mpm_w1, mpm_b1, mla_w0);
    k_cb<<<128, 128>>>(tokenizer, mla_w0);
    k_dcm<<<64, 128>>>();
    k_wt<<<128, 256>>>(mla_w1);
    k_ape4<<<2048, 128>>>(heading, position,
                          ape_w0, ape_b0, ape_g0, ape_t0,
                          ape_w1, ape_b1, ape_g1, ape_t1,
                          ape_w2, ape_b2, mla_w0, mla_b0);
    {
        dim3 gdots(128, 3);
        k_dots<<<gdots, 256>>>();
    }
    k_main<<<4096, 256, SMEM_BYTES>>>(map_latent, mla_b1, mla_g0, mla_t0, out);
}